// round 10
// baseline (speedup 1.0000x reference)
#include <cuda_runtime.h>
#include <cuda_bf16.h>
#include <cstdint>
#include <cstddef>

// ===========================================================================
// Who2com forward — split-bf16 mma.sync implicit-GEMM convs.
// R10: software-pipelined fragment loads (double-buffered A and B ldsm,
// prefetched one step ahead) to close the 59% -> ~100% tensor-pipe gap.
// Conv structure (MTILE=64, 2 stages, 2 CTAs/SM) identical to R9.
// ===========================================================================

__device__ __forceinline__ uint32_t smem_to_u32(const void* p) {
    uint32_t a;
    asm("{ .reg .u64 t; cvta.to.shared.u64 t, %1; cvt.u32.u64 %0, t; }"
        : "=r"(a) : "l"(p));
    return a;
}
__device__ __forceinline__ void ldsm_x4(uint32_t (&r)[4], uint32_t addr) {
    asm volatile("ldmatrix.sync.aligned.m8n8.x4.shared.b16 {%0,%1,%2,%3}, [%4];"
                 : "=r"(r[0]), "=r"(r[1]), "=r"(r[2]), "=r"(r[3]) : "r"(addr));
}
__device__ __forceinline__ void mma_bf16(float (&d)[4], const uint32_t (&a)[4],
                                         uint32_t b0, uint32_t b1) {
    asm volatile(
        "mma.sync.aligned.m16n8k16.row.col.f32.bf16.bf16.f32 "
        "{%0,%1,%2,%3}, {%4,%5,%6,%7}, {%8,%9}, {%0,%1,%2,%3};"
        : "+f"(d[0]), "+f"(d[1]), "+f"(d[2]), "+f"(d[3])
        : "r"(a[0]), "r"(a[1]), "r"(a[2]), "r"(a[3]), "r"(b0), "r"(b1));
}
__device__ __forceinline__ uint32_t pack_bf2(__nv_bfloat16 a, __nv_bfloat16 b) {
    __nv_bfloat162 t = __halves2bfloat162(a, b);
    return *reinterpret_cast<uint32_t*>(&t);
}
__device__ __forceinline__ void cp16(uint32_t dst, const void* src, bool v) {
    asm volatile("cp.async.cg.shared.global [%0], [%1], 16, %2;"
                 :: "r"(dst), "l"(src), "r"(v ? 16u : 0u) : "memory");
}
#define CP_COMMIT() asm volatile("cp.async.commit_group;" ::: "memory")

// ---------------------------------------------------------------------------
// Scratch
// ---------------------------------------------------------------------------
__device__ __align__(16) __nv_bfloat16 g_a0h[(size_t)160 * 256 * 256];
__device__ __align__(16) __nv_bfloat16 g_a0l[(size_t)160 * 256 * 256];
__device__ __align__(16) __nv_bfloat16 g_b1h[(size_t)160 * 256 * 512];
__device__ __align__(16) __nv_bfloat16 g_b1l[(size_t)160 * 256 * 512];
__device__ __align__(16) __nv_bfloat16 g_b2h[(size_t)160 * 256 * 256];
__device__ __align__(16) __nv_bfloat16 g_b2l[(size_t)160 * 256 * 256];
__device__ __align__(16) __nv_bfloat16 g_b3h[(size_t)160 * 64 * 256];
__device__ __align__(16) __nv_bfloat16 g_b3l[(size_t)160 * 64 * 256];
__device__ __align__(16) __nv_bfloat16 g_b4h[(size_t)160 * 64 * 256];
__device__ __align__(16) __nv_bfloat16 g_b4l[(size_t)160 * 64 * 256];
__device__ float g_feat[(size_t)160 * 4096];
__device__ float g_m1k[160 * 256], g_m1q[160 * 256];
__device__ float g_m2k[160 * 128], g_m2q[160 * 128];
__device__ float g_keys[160 * 1024];
__device__ float g_qrys[160 * 32];
__device__ float g_qq[160 * 1024];
__device__ float g_wf[32 * 5];
__device__ __align__(16) __nv_bfloat16 g_w1h[512 * 2304], g_w1l[512 * 2304];
__device__ __align__(16) __nv_bfloat16 g_w2h[256 * 4608], g_w2l[256 * 4608];
__device__ __align__(16) __nv_bfloat16 g_w3h[256 * 2304], g_w3l[256 * 2304];
__device__ __align__(16) __nv_bfloat16 g_w4h[256 * 2304], g_w4l[256 * 2304];
__device__ __align__(16) __nv_bfloat16 g_w5h[256 * 2304], g_w5l[256 * 2304];

// ---------------------------------------------------------------------------
// Merged weight prep: all 5 conv layers in one launch.
// ---------------------------------------------------------------------------
struct WPrepDesc {
    const float* src;
    __nv_bfloat16* hi;
    __nv_bfloat16* lo;
    int cin;
    int total;
    int base;
};

__global__ void wprep_all_kernel(WPrepDesc d0, WPrepDesc d1, WPrepDesc d2,
                                 WPrepDesc d3, WPrepDesc d4, int grand)
{
    WPrepDesc ds[5] = {d0, d1, d2, d3, d4};
    for (int g = blockIdx.x * blockDim.x + threadIdx.x; g < grand;
         g += gridDim.x * blockDim.x) {
        int li = 0;
#pragma unroll
        for (int t = 1; t < 5; t++)
            if (g >= ds[t].base) li = t;
        const WPrepDesc& d = ds[li];
        int idx = g - d.base;
        int cin9 = d.cin * 9;
        int co = idx / cin9;
        int rem = idx - co * cin9;
        int ci = rem / 9, tap = rem - ci * 9;
        float v = d.src[idx];
        __nv_bfloat16 h = __float2bfloat16(v);
        __nv_bfloat16 l = __float2bfloat16(v - __bfloat162float(h));
        size_t dd = (size_t)co * cin9 + tap * d.cin + ci;
        d.hi[dd] = h; d.lo[dd] = l;
    }
}

// bevs NCHW fp32 -> NHWC hi/lo bf16.
__global__ void actsplit_kernel(const float* __restrict__ in,
                                __nv_bfloat16* __restrict__ oh,
                                __nv_bfloat16* __restrict__ ol)
{
    __shared__ float s[32][257];
    int n = blockIdx.x, c0 = blockIdx.y * 32;
    int tid = threadIdx.x;
#pragma unroll
    for (int it = 0; it < 32; it++)
        s[it][tid] = in[((size_t)n * 256 + c0 + it) * 256 + tid];
    __syncthreads();
    int ci = tid & 31, p0 = tid >> 5;
#pragma unroll
    for (int pp = 0; pp < 32; pp++) {
        int pix = p0 + pp * 8;
        float v = s[ci][pix];
        __nv_bfloat16 h = __float2bfloat16(v);
        __nv_bfloat16 l = __float2bfloat16(v - __bfloat162float(h));
        size_t o = ((size_t)n * 256 + pix) * 256 + c0 + ci;
        oh[o] = h; ol[o] = l;
    }
}

// ---------------------------------------------------------------------------
// Implicit-GEMM conv3x3 (pad=1) + affine + ReLU, split-bf16 mma.sync.
// K-chunks of 64 (144B pitch), circular 2-stage cp.async pipeline, one
// __syncthreads per chunk, software-pipelined ldsm fragments.
// ---------------------------------------------------------------------------
static constexpr int SPB = 144;

template <int CIN, int COUT, int HIN, int WIN, int STRIDE, int OUTMODE,
          int MTILE, int STAGES, int MINCTA>
__global__ void __launch_bounds__(256, MINCTA)
convMMA_kernel(const __nv_bfloat16* __restrict__ aH, const __nv_bfloat16* __restrict__ aL,
               const __nv_bfloat16* __restrict__ wH, const __nv_bfloat16* __restrict__ wL,
               const float* __restrict__ scale, const float* __restrict__ shift,
               __nv_bfloat16* __restrict__ oH, __nv_bfloat16* __restrict__ oL,
               float* __restrict__ oF)
{
    constexpr int HO   = (HIN - 1) / STRIDE + 1;
    constexpr int WO   = (WIN - 1) / STRIDE + 1;
    constexpr int MPIX = HO * WO;
    constexpr int NIMG = (MPIX >= MTILE) ? 1 : (MTILE / MPIX);
    constexpr int NT   = COUT / 128;
    constexpr int KTOT = 9 * CIN;
    constexpr int CPT  = CIN / 64;
    constexpr int NCH  = 9 * CPT;
    constexpr int MW   = MTILE / 32;
    constexpr int NW   = 8 / MW;
    constexpr int NCPW = 128 / NW;
    constexpr int NT2  = NCPW / 16;
    constexpr int STB  = (MTILE + 128) * 2 * SPB;
    constexpr int A_LO = MTILE * SPB;
    constexpr int B_HI = MTILE * 2 * SPB;
    constexpr int B_LO = B_HI + 128 * SPB;
    constexpr int RT   = (MTILE + 128) * 16;
    constexpr int TSTEPS = 4 * NT2;          // flattened (ks, nt2)

    extern __shared__ char smem[];
    const uint32_t sb = smem_to_u32(smem);

    const int tid = threadIdx.x, wid = tid >> 5, lane = tid & 31;
    const int mt  = blockIdx.x / NT;
    const int co0 = (blockIdx.x % NT) * 128;
    const int n0  = blockIdx.y * NIMG;
    const int wm  = wid % MW;
    const int wn  = wid / MW;

    auto issue = [&](int c) {
        const uint32_t st = sb + (uint32_t)(c % STAGES) * STB;
        const int tap = c / CPT;
        const int ci0 = (c - tap * CPT) * 64;
        const int dy = tap / 3 - 1, dx = tap % 3 - 1;
#pragma unroll
        for (int i = tid; i < RT; i += 256) {
            const int row  = i >> 4;
            const int seg  = i & 7;
            const int half = (i >> 3) & 1;
            if (row < MTILE) {
                int g = mt * MTILE + row;
                int img = g / MPIX, pix = g % MPIX;
                int oh = pix / WO, ow = pix - oh * WO;
                int ih = oh * STRIDE + dy, iw = ow * STRIDE + dx;
                bool v = ((unsigned)ih < (unsigned)HIN) && ((unsigned)iw < (unsigned)WIN);
                int ihs = v ? ih : 0, iws = v ? iw : 0;
                size_t aoff = (((size_t)(n0 + img) * HIN + ihs) * WIN + iws) * CIN
                              + ci0 + seg * 8;
                uint32_t ad = st + (uint32_t)half * A_LO + (uint32_t)row * SPB + seg * 16;
                cp16(ad, (half ? aL : aH) + aoff, v);
            } else {
                int r2 = row - MTILE;
                size_t woff = (size_t)(co0 + r2) * KTOT + (size_t)c * 64 + seg * 8;
                uint32_t bd = st + B_HI + (uint32_t)half * (128 * SPB)
                              + (uint32_t)r2 * SPB + seg * 16;
                cp16(bd, (half ? wL : wH) + woff, true);
            }
        }
        CP_COMMIT();
    };

    float acc[2][NT2 * 2][4];
#pragma unroll
    for (int a = 0; a < 2; a++)
#pragma unroll
        for (int b = 0; b < NT2 * 2; b++)
#pragma unroll
            for (int c = 0; c < 4; c++) acc[a][b][c] = 0.f;

#pragma unroll
    for (int p = 0; p < STAGES - 1; p++) issue(p);

    for (int c = 0; c < NCH; c++) {
        asm volatile("cp.async.wait_group %0;" :: "n"(STAGES - 2) : "memory");
        __syncthreads();
        if (c + STAGES - 1 < NCH) issue(c + STAGES - 1);
        else CP_COMMIT();

        const uint32_t st  = sb + (uint32_t)(c % STAGES) * STB;
        const uint32_t sAh = st, sAl = st + A_LO, sBh = st + B_HI, sBl = st + B_LO;

        // ---- software-pipelined fragment loop over (ks, nt2) ----
        uint32_t aHf[2][2][4], aLf[2][2][4];   // [buf][m2][reg]
        uint32_t bHf[2][4], bLf[2][4];          // [buf][reg]

        auto loadA = [&](int ks, int buf) {
            const uint32_t acol = (uint32_t)ks * 32u + ((lane >> 4) << 4);
#pragma unroll
            for (int m2 = 0; m2 < 2; m2++) {
                uint32_t arow = (uint32_t)(wm * 32 + m2 * 16 + (lane & 15));
                ldsm_x4(aHf[buf][m2], sAh + arow * SPB + acol);
                ldsm_x4(aLf[buf][m2], sAl + arow * SPB + acol);
            }
        };
        auto loadB = [&](int t, int buf) {
            const int ks = t / NT2, nt2 = t % NT2;
            const uint32_t bcol = (uint32_t)ks * 32u + (((lane >> 3) & 1) << 4);
            const uint32_t brow = (uint32_t)(wn * NCPW + nt2 * 16 +
                                             ((lane >> 4) << 3) + (lane & 7));
            ldsm_x4(bHf[buf], sBh + brow * SPB + bcol);
            ldsm_x4(bLf[buf], sBl + brow * SPB + bcol);
        };

        loadA(0, 0);
        loadB(0, 0);
#pragma unroll
        for (int t = 0; t < TSTEPS; t++) {
            const int ks = t / NT2, nt2 = t % NT2;
            const int cb = t & 1;
            if (t + 1 < TSTEPS) loadB(t + 1, cb ^ 1);
            if (nt2 == 0 && ks + 1 < 4) loadA(ks + 1, (ks + 1) & 1);
            const int ab = ks & 1;
#pragma unroll
            for (int m2 = 0; m2 < 2; m2++) {
                mma_bf16(acc[m2][nt2 * 2],     aHf[ab][m2], bHf[cb][0], bHf[cb][1]);
                mma_bf16(acc[m2][nt2 * 2 + 1], aHf[ab][m2], bHf[cb][2], bHf[cb][3]);
                mma_bf16(acc[m2][nt2 * 2],     aLf[ab][m2], bHf[cb][0], bHf[cb][1]);
                mma_bf16(acc[m2][nt2 * 2 + 1], aLf[ab][m2], bHf[cb][2], bHf[cb][3]);
                mma_bf16(acc[m2][nt2 * 2],     aHf[ab][m2], bLf[cb][0], bLf[cb][1]);
                mma_bf16(acc[m2][nt2 * 2 + 1], aHf[ab][m2], bLf[cb][2], bLf[cb][3]);
            }
        }
    }

    if (OUTMODE == 0) {
#pragma unroll
        for (int m2 = 0; m2 < 2; m2++) {
            int mA = wm * 32 + m2 * 16 + (lane >> 2);
            int gA = mt * MTILE + mA;
            int gB = gA + 8;
            size_t rowA = ((size_t)(n0 + gA / MPIX) * MPIX + gA % MPIX) * COUT;
            size_t rowB = ((size_t)(n0 + gB / MPIX) * MPIX + gB % MPIX) * COUT;
#pragma unroll
            for (int j = 0; j < NT2 * 2; j++) {
                int co = co0 + wn * NCPW + j * 8 + (lane & 3) * 2;
                float s0 = __ldg(scale + co), s1 = __ldg(scale + co + 1);
                float t0 = __ldg(shift + co), t1 = __ldg(shift + co + 1);
                float v0 = fmaxf(fmaf(acc[m2][j][0], s0, t0), 0.f);
                float v1 = fmaxf(fmaf(acc[m2][j][1], s1, t1), 0.f);
                float v2 = fmaxf(fmaf(acc[m2][j][2], s0, t0), 0.f);
                float v3 = fmaxf(fmaf(acc[m2][j][3], s1, t1), 0.f);
                __nv_bfloat16 h0 = __float2bfloat16(v0), h1 = __float2bfloat16(v1);
                __nv_bfloat16 h2 = __float2bfloat16(v2), h3 = __float2bfloat16(v3);
                __nv_bfloat16 l0 = __float2bfloat16(v0 - __bfloat162float(h0));
                __nv_bfloat16 l1 = __float2bfloat16(v1 - __bfloat162float(h1));
                __nv_bfloat16 l2 = __float2bfloat16(v2 - __bfloat162float(h2));
                __nv_bfloat16 l3 = __float2bfloat16(v3 - __bfloat162float(h3));
                *reinterpret_cast<uint32_t*>(oH + rowA + co) = pack_bf2(h0, h1);
                *reinterpret_cast<uint32_t*>(oL + rowA + co) = pack_bf2(l0, l1);
                *reinterpret_cast<uint32_t*>(oH + rowB + co) = pack_bf2(h2, h3);
                *reinterpret_cast<uint32_t*>(oL + rowB + co) = pack_bf2(l2, l3);
            }
        }
    } else {
        constexpr int OPITCH = MTILE + 4;
        float* sOut = reinterpret_cast<float*>(smem);
        __syncthreads();
#pragma unroll
        for (int m2 = 0; m2 < 2; m2++) {
#pragma unroll
            for (int j = 0; j < NT2 * 2; j++) {
                int m = wm * 32 + m2 * 16 + (lane >> 2);
                int nn = wn * NCPW + j * 8 + (lane & 3) * 2;
                sOut[(size_t)nn * OPITCH + m]           = acc[m2][j][0];
                sOut[(size_t)(nn + 1) * OPITCH + m]     = acc[m2][j][1];
                sOut[(size_t)nn * OPITCH + m + 8]       = acc[m2][j][2];
                sOut[(size_t)(nn + 1) * OPITCH + m + 8] = acc[m2][j][3];
            }
        }
        __syncthreads();
        int row = tid >> 1, half = tid & 1;
        int co = co0 + row;
        float s = __ldg(scale + co), t = __ldg(shift + co);
#pragma unroll
        for (int q = 0; q < MTILE / 8; q++) {
            int m = half * (MTILE / 2) + q * 4;
            float4 v = *reinterpret_cast<float4*>(&sOut[(size_t)row * OPITCH + m]);
            v.x = fmaxf(fmaf(v.x, s, t), 0.f);
            v.y = fmaxf(fmaf(v.y, s, t), 0.f);
            v.z = fmaxf(fmaf(v.z, s, t), 0.f);
            v.w = fmaxf(fmaf(v.w, s, t), 0.f);
            int g = mt * MTILE + m;
            int img = g / MPIX, pix = g % MPIX;
            *reinterpret_cast<float4*>(
                &oF[((size_t)(n0 + img) * COUT + co) * MPIX + pix]) = v;
        }
    }
}

// ---------------------------------------------------------------------------
// Warp-tile GEMV over TWO independent (X,W,b,Y,N) sets in one launch.
// ---------------------------------------------------------------------------
__global__ void warptile2_kernel(const float* __restrict__ X1, const float* __restrict__ W1,
                                 const float* __restrict__ B1, float* __restrict__ Y1, int N1,
                                 const float* __restrict__ X2, const float* __restrict__ W2,
                                 const float* __restrict__ B2, float* __restrict__ Y2, int N2,
                                 int M, int K, int doRelu)
{
    int gw   = (blockIdx.x * blockDim.x + threadIdx.x) >> 5;
    int lane = threadIdx.x & 31;
    int nWtot = (N1 + N2) >> 3;
    int mtile = gw / nWtot, ntile = gw - mtile * nWtot;
    if (mtile * 4 >= M) return;
    const float *X, *W, *Bb;
    float* Y;
    int N, nt;
    if (ntile < (N1 >> 3)) { X = X1; W = W1; Bb = B1; Y = Y1; N = N1; nt = ntile; }
    else { X = X2; W = W2; Bb = B2; Y = Y2; N = N2; nt = ntile - (N1 >> 3); }
    const float* x0 = X + (size_t)(mtile * 4) * K;
    const float* w0 = W + (size_t)(nt * 8) * K;
    float acc[4][8];
#pragma unroll
    for (int i = 0; i < 4; i++)
#pragma unroll
        for (int j = 0; j < 8; j++) acc[i][j] = 0.f;
    for (int k = lane; k < K; k += 32) {
        float xv[4], wv[8];
#pragma unroll
        for (int i = 0; i < 4; i++) xv[i] = x0[(size_t)i * K + k];
#pragma unroll
        for (int j = 0; j < 8; j++) wv[j] = w0[(size_t)j * K + k];
#pragma unroll
        for (int i = 0; i < 4; i++)
#pragma unroll
            for (int j = 0; j < 8; j++) acc[i][j] = fmaf(xv[i], wv[j], acc[i][j]);
    }
#pragma unroll
    for (int o = 16; o; o >>= 1)
#pragma unroll
        for (int i = 0; i < 4; i++)
#pragma unroll
            for (int j = 0; j < 8; j++)
                acc[i][j] += __shfl_xor_sync(0xffffffffu, acc[i][j], o);
    int i = lane >> 3, j = lane & 7;
    float v = acc[i][j] + Bb[nt * 8 + j];
    if (doRelu) v = fmaxf(v, 0.f);
    Y[(size_t)(mtile * 4 + i) * N + nt * 8 + j] = v;
}

__global__ void warptile_kernel(const float* __restrict__ X, const float* __restrict__ W,
                                const float* __restrict__ bias, float* __restrict__ Y,
                                int M, int N, int K, int doRelu)
{
    int gw   = (blockIdx.x * blockDim.x + threadIdx.x) >> 5;
    int lane = threadIdx.x & 31;
    int nW = N >> 3;
    int mtile = gw / nW, ntile = gw - mtile * nW;
    if (mtile * 4 >= M) return;
    const float* x0 = X + (size_t)(mtile * 4) * K;
    const float* w0 = W + (size_t)(ntile * 8) * K;
    float acc[4][8];
#pragma unroll
    for (int i = 0; i < 4; i++)
#pragma unroll
        for (int j = 0; j < 8; j++) acc[i][j] = 0.f;
    for (int k = lane; k < K; k += 32) {
        float xv[4], wv[8];
#pragma unroll
        for (int i = 0; i < 4; i++) xv[i] = x0[(size_t)i * K + k];
#pragma unroll
        for (int j = 0; j < 8; j++) wv[j] = w0[(size_t)j * K + k];
#pragma unroll
        for (int i = 0; i < 4; i++)
#pragma unroll
            for (int j = 0; j < 8; j++) acc[i][j] = fmaf(xv[i], wv[j], acc[i][j]);
    }
#pragma unroll
    for (int o = 16; o; o >>= 1)
#pragma unroll
        for (int i = 0; i < 4; i++)
#pragma unroll
            for (int j = 0; j < 8; j++)
                acc[i][j] += __shfl_xor_sync(0xffffffffu, acc[i][j], o);
    int i = lane >> 3, j = lane & 7;
    float v = acc[i][j] + bias[ntile * 8 + j];
    if (doRelu) v = fmaxf(v, 0.f);
    Y[(size_t)(mtile * 4 + i) * N + ntile * 8 + j] = v;
}

// ---------------------------------------------------------------------------
// Attention + softmax -> fuse weights; final fuse.
// ---------------------------------------------------------------------------
__global__ void attn_kernel(const float* __restrict__ keys, const float* __restrict__ qq,
                            float* __restrict__ wf)
{
    int b = blockIdx.x;
    __shared__ float sA[5][5];
    int warp = threadIdx.x >> 5, lane = threadIdx.x & 31;
    for (int e = warp; e < 25; e += 8) {
        int i = e / 5, j = e - i * 5;
        const float4* kr = (const float4*)(keys + (size_t)(i * 32 + b) * 1024);
        const float4* qr = (const float4*)(qq + (size_t)(j * 32 + b) * 1024);
        float acc = 0.f;
        for (int k = lane; k < 256; k += 32) {
            float4 a = kr[k], c = qr[k];
            acc += a.x * c.x + a.y * c.y + a.z * c.z + a.w * c.w;
        }
#pragma unroll
        for (int o = 16; o; o >>= 1) acc += __shfl_xor_sync(0xffffffffu, acc, o);
        if (lane == 0) sA[i][j] = acc;
    }
    __syncthreads();
    if (threadIdx.x == 0) {
        float w[5] = {0.f, 0.f, 0.f, 0.f, 0.f};
        for (int j = 0; j < 5; j++) {
            float dd[4], mx = -1e30f;
            for (int r = 0; r < 4; r++) {
                dd[r] = (j > r) ? sA[r][j] : sA[r + 1][j];
                mx = fmaxf(mx, dd[r]);
            }
            float s = 0.f;
            for (int r = 0; r < 4; r++) { dd[r] = expf(dd[r] - mx); s += dd[r]; }
            float inv = 1.f / s;
            for (int r = 0; r < 4; r++) {
                int i = (j > r) ? r : r + 1;
                w[i] += dd[r] * inv;
            }
        }
        for (int i = 0; i < 5; i++) wf[b * 5 + i] = w[i] * 0.2f;
    }
}

__global__ void fuse_kernel(const float* __restrict__ bevs, const float* __restrict__ wf,
                            float* __restrict__ out)
{
    const int CHW = 256 * 16 * 16;
    int idx = blockIdx.x * blockDim.x + threadIdx.x;
    if (idx >= 32 * CHW) return;
    int b   = idx / CHW;
    int chw = idx - b * CHW;
    const float* base = bevs + ((size_t)b * 5) * CHW + chw;
    float acc = 0.f;
#pragma unroll
    for (int k = 0; k < 5; k++) acc += wf[b * 5 + k] * base[(size_t)k * CHW];
    out[idx] = acc;
}

// ---------------------------------------------------------------------------
extern "C" void kernel_launch(void* const* d_in, const int* in_sizes, int n_in,
                              void* d_out, int out_size)
{
    (void)in_sizes; (void)n_in; (void)out_size;
    const float* bevs = (const float*)d_in[0];
    const float *cw[5], *cs[5], *ct[5];
    for (int i = 0; i < 5; i++) {
        cw[i] = (const float*)d_in[1 + 3 * i];
        cs[i] = (const float*)d_in[2 + 3 * i];
        ct[i] = (const float*)d_in[3 + 3 * i];
    }
    const float* kw1 = (const float*)d_in[16]; const float* kb1 = (const float*)d_in[17];
    const float* kw2 = (const float*)d_in[18]; const float* kb2 = (const float*)d_in[19];
    const float* kw3 = (const float*)d_in[20]; const float* kb3 = (const float*)d_in[21];
    const float* qw1 = (const float*)d_in[22]; const float* qb1 = (const float*)d_in[23];
    const float* qw2 = (const float*)d_in[24]; const float* qb2 = (const float*)d_in[25];
    const float* qw3 = (const float*)d_in[26]; const float* qb3 = (const float*)d_in[27];
    const float* aw  = (const float*)d_in[28]; const float* ab  = (const float*)d_in[29];
    float* out = (float*)d_out;

    __nv_bfloat16 *a0h, *a0l, *b1h, *b1l, *b2h, *b2l, *b3h, *b3l, *b4h, *b4l;
    cudaGetSymbolAddress((void**)&a0h, g_a0h); cudaGetSymbolAddress((void**)&a0l, g_a0l);
    cudaGetSymbolAddress((void**)&b1h, g_b1h); cudaGetSymbolAddress((void**)&b1l, g_b1l);
    cudaGetSymbolAddress((void**)&b2h, g_b2h); cudaGetSymbolAddress((void**)&b2l, g_b2l);
    cudaGetSymbolAddress((void**)&b3h, g_b3h); cudaGetSymbolAddress((void**)&b3l, g_b3l);
    cudaGetSymbolAddress((void**)&b4h, g_b4h); cudaGetSymbolAddress((void**)&b4l, g_b4l);
    float *feat, *m1k, *m1q, *m2k, *m2q, *keys, *qrys, *qq, *wf;
    cudaGetSymbolAddress((void**)&feat, g_feat);
    cudaGetSymbolAddress((void**)&m1k, g_m1k);
    cudaGetSymbolAddress((void**)&m1q, g_m1q);
    cudaGetSymbolAddress((void**)&m2k, g_m2k);
    cudaGetSymbolAddress((void**)&m2q, g_m2q);
    cudaGetSymbolAddress((void**)&keys, g_keys);
    cudaGetSymbolAddress((void**)&qrys, g_qrys);
    cudaGetSymbolAddress((void**)&qq, g_qq);
    cudaGetSymbolAddress((void**)&wf, g_wf);
    __nv_bfloat16 *w1h, *w1l, *w2h, *w2l, *w3h, *w3l, *w4h, *w4l, *w5h, *w5l;
    cudaGetSymbolAddress((void**)&w1h, g_w1h); cudaGetSymbolAddress((void**)&w1l, g_w1l);
    cudaGetSymbolAddress((void**)&w2h, g_w2h); cudaGetSymbolAddress((void**)&w2l, g_w2l);
    cudaGetSymbolAddress((void**)&w3h, g_w3h); cudaGetSymbolAddress((void**)&w3l, g_w3l);
    cudaGetSymbolAddress((void**)&w4h, g_w4h); cudaGetSymbolAddress((void**)&w4l, g_w4l);
    cudaGetSymbolAddress((void**)&w5h, g_w5h); cudaGetSymbolAddress((void**)&w5l, g_w5l);

    constexpr int SMEM_S = 2 * 55296;   // 110592, 2 CTAs/SM

    cudaFuncSetAttribute(convMMA_kernel<256, 512, 16, 16, 1, 0, 64, 2, 2>,
                         cudaFuncAttributeMaxDynamicSharedMemorySize, SMEM_S);
    cudaFuncSetAttribute(convMMA_kernel<512, 256, 16, 16, 1, 0, 64, 2, 2>,
                         cudaFuncAttributeMaxDynamicSharedMemorySize, SMEM_S);
    cudaFuncSetAttribute(convMMA_kernel<256, 256, 16, 16, 2, 0, 64, 2, 2>,
                         cudaFuncAttributeMaxDynamicSharedMemorySize, SMEM_S);
    cudaFuncSetAttribute(convMMA_kernel<256, 256, 8, 8, 1, 0, 64, 2, 2>,
                         cudaFuncAttributeMaxDynamicSharedMemorySize, SMEM_S);
    cudaFuncSetAttribute(convMMA_kernel<256, 256, 8, 8, 2, 1, 64, 2, 2>,
                         cudaFuncAttributeMaxDynamicSharedMemorySize, SMEM_S);

    // ---- launch 0: all weight preps in one kernel ----
    {
        int t1 = 512 * 2304, t2 = 256 * 4608, t3 = 256 * 2304;
        WPrepDesc d0 = {cw[0], w1h, w1l, 256, t1, 0};
        WPrepDesc d1 = {cw[1], w2h, w2l, 512, t2, t1};
        WPrepDesc d2 = {cw[2], w3h, w3l, 256, t3, t1 + t2};
        WPrepDesc d3 = {cw[3], w4h, w4l, 256, t3, t1 + t2 + t3};
        WPrepDesc d4 = {cw[4], w5h, w5l, 256, t3, t1 + t2 + 2 * t3};
        int grand = t1 + t2 + 3 * t3;
        wprep_all_kernel<<<1184, 256>>>(d0, d1, d2, d3, d4, grand);
    }
    // ---- launch 1: bevs split ----
    actsplit_kernel<<<dim3(160, 8), 256>>>(bevs, a0h, a0l);

    // ---- launches 2..6: conv stack, all MTILE=64 @ 2 CTAs/SM ----
    convMMA_kernel<256, 512, 16, 16, 1, 0, 64, 2, 2><<<dim3(16, 160), 256, SMEM_S>>>(
        a0h, a0l, w1h, w1l, cs[0], ct[0], b1h, b1l, nullptr);
    convMMA_kernel<512, 256, 16, 16, 1, 0, 64, 2, 2><<<dim3(8, 160), 256, SMEM_S>>>(
        b1h, b1l, w2h, w2l, cs[1], ct[1], b2h, b2l, nullptr);
    convMMA_kernel<256, 256, 16, 16, 2, 0, 64, 2, 2><<<dim3(2, 160), 256, SMEM_S>>>(
        b2h, b2l, w3h, w3l, cs[2], ct[2], b3h, b3l, nullptr);
    convMMA_kernel<256, 256, 8, 8, 1, 0, 64, 2, 2><<<dim3(2, 160), 256, SMEM_S>>>(
        b3h, b3l, w4h, w4l, cs[3], ct[3], b4h, b4l, nullptr);
    convMMA_kernel<256, 256, 8, 8, 2, 1, 64, 2, 2><<<dim3(2, 40), 256, SMEM_S>>>(
        b4h, b4l, w5h, w5l, cs[4], ct[4], nullptr, nullptr, feat);

    // ---- fused k/q tail ----
    auto wt2 = [&](const float* X1, const float* W1, const float* B1, float* Y1, int N1,
                   const float* X2, const float* W2, const float* B2, float* Y2, int N2,
                   int M, int K, int relu) {
        int warps = (M / 4) * ((N1 + N2) / 8);
        warptile2_kernel<<<(warps + 7) / 8, 256>>>(X1, W1, B1, Y1, N1,
                                                   X2, W2, B2, Y2, N2, M, K, relu);
    };
    wt2(feat, kw1, kb1, m1k, 256, feat, qw1, qb1, m1q, 256, 160, 4096, 1);
    wt2(m1k, kw2, kb2, m2k, 128, m1q, qw2, qb2, m2q, 128, 160, 256, 1);
    wt2(m2k, kw3, kb3, keys, 1024, m2q, qw3, qb3, qrys, 32, 160, 128, 0);
    {
        int warps = (160 / 4) * (1024 / 8);
        warptile_kernel<<<(warps + 7) / 8, 256>>>(qrys, aw, ab, qq, 160, 1024, 32, 0);
    }

    attn_kernel<<<32, 256>>>(keys, qq, wf);
    fuse_kernel<<<(32 * 256 * 16 * 16 + 255) / 256, 256>>>(bevs, wf, out);
}

// round 11
// speedup vs baseline: 1.5102x; 1.5102x over previous
#include <cuda_runtime.h>
#include <cuda_bf16.h>
#include <cstdint>
#include <cstddef>

// ===========================================================================
// Who2com forward — split-bf16 mma.sync implicit-GEMM convs.
// R11: revert to R9 structure (best: 2048us); single local change in the
// fragment loop: batch all 8 ldsm per ks before the 24 MMAs (same
// per-accumulator operand order -> bitwise-identical results).
// ===========================================================================

__device__ __forceinline__ uint32_t smem_to_u32(const void* p) {
    uint32_t a;
    asm("{ .reg .u64 t; cvta.to.shared.u64 t, %1; cvt.u32.u64 %0, t; }"
        : "=r"(a) : "l"(p));
    return a;
}
__device__ __forceinline__ void ldsm_x4(uint32_t (&r)[4], uint32_t addr) {
    asm volatile("ldmatrix.sync.aligned.m8n8.x4.shared.b16 {%0,%1,%2,%3}, [%4];"
                 : "=r"(r[0]), "=r"(r[1]), "=r"(r[2]), "=r"(r[3]) : "r"(addr));
}
__device__ __forceinline__ void mma_bf16(float (&d)[4], const uint32_t (&a)[4],
                                         uint32_t b0, uint32_t b1) {
    asm volatile(
        "mma.sync.aligned.m16n8k16.row.col.f32.bf16.bf16.f32 "
        "{%0,%1,%2,%3}, {%4,%5,%6,%7}, {%8,%9}, {%0,%1,%2,%3};"
        : "+f"(d[0]), "+f"(d[1]), "+f"(d[2]), "+f"(d[3])
        : "r"(a[0]), "r"(a[1]), "r"(a[2]), "r"(a[3]), "r"(b0), "r"(b1));
}
__device__ __forceinline__ uint32_t pack_bf2(__nv_bfloat16 a, __nv_bfloat16 b) {
    __nv_bfloat162 t = __halves2bfloat162(a, b);
    return *reinterpret_cast<uint32_t*>(&t);
}
__device__ __forceinline__ void cp16(uint32_t dst, const void* src, bool v) {
    asm volatile("cp.async.cg.shared.global [%0], [%1], 16, %2;"
                 :: "r"(dst), "l"(src), "r"(v ? 16u : 0u) : "memory");
}
#define CP_COMMIT() asm volatile("cp.async.commit_group;" ::: "memory")

// ---------------------------------------------------------------------------
// Scratch
// ---------------------------------------------------------------------------
__device__ __align__(16) __nv_bfloat16 g_a0h[(size_t)160 * 256 * 256];
__device__ __align__(16) __nv_bfloat16 g_a0l[(size_t)160 * 256 * 256];
__device__ __align__(16) __nv_bfloat16 g_b1h[(size_t)160 * 256 * 512];
__device__ __align__(16) __nv_bfloat16 g_b1l[(size_t)160 * 256 * 512];
__device__ __align__(16) __nv_bfloat16 g_b2h[(size_t)160 * 256 * 256];
__device__ __align__(16) __nv_bfloat16 g_b2l[(size_t)160 * 256 * 256];
__device__ __align__(16) __nv_bfloat16 g_b3h[(size_t)160 * 64 * 256];
__device__ __align__(16) __nv_bfloat16 g_b3l[(size_t)160 * 64 * 256];
__device__ __align__(16) __nv_bfloat16 g_b4h[(size_t)160 * 64 * 256];
__device__ __align__(16) __nv_bfloat16 g_b4l[(size_t)160 * 64 * 256];
__device__ float g_feat[(size_t)160 * 4096];
__device__ float g_m1k[160 * 256], g_m1q[160 * 256];
__device__ float g_m2k[160 * 128], g_m2q[160 * 128];
__device__ float g_keys[160 * 1024];
__device__ float g_qrys[160 * 32];
__device__ float g_qq[160 * 1024];
__device__ float g_wf[32 * 5];
__device__ __align__(16) __nv_bfloat16 g_w1h[512 * 2304], g_w1l[512 * 2304];
__device__ __align__(16) __nv_bfloat16 g_w2h[256 * 4608], g_w2l[256 * 4608];
__device__ __align__(16) __nv_bfloat16 g_w3h[256 * 2304], g_w3l[256 * 2304];
__device__ __align__(16) __nv_bfloat16 g_w4h[256 * 2304], g_w4l[256 * 2304];
__device__ __align__(16) __nv_bfloat16 g_w5h[256 * 2304], g_w5l[256 * 2304];

// ---------------------------------------------------------------------------
// Merged weight prep: all 5 conv layers in one launch.
// ---------------------------------------------------------------------------
struct WPrepDesc {
    const float* src;
    __nv_bfloat16* hi;
    __nv_bfloat16* lo;
    int cin;
    int total;
    int base;
};

__global__ void wprep_all_kernel(WPrepDesc d0, WPrepDesc d1, WPrepDesc d2,
                                 WPrepDesc d3, WPrepDesc d4, int grand)
{
    WPrepDesc ds[5] = {d0, d1, d2, d3, d4};
    for (int g = blockIdx.x * blockDim.x + threadIdx.x; g < grand;
         g += gridDim.x * blockDim.x) {
        int li = 0;
#pragma unroll
        for (int t = 1; t < 5; t++)
            if (g >= ds[t].base) li = t;
        const WPrepDesc& d = ds[li];
        int idx = g - d.base;
        int cin9 = d.cin * 9;
        int co = idx / cin9;
        int rem = idx - co * cin9;
        int ci = rem / 9, tap = rem - ci * 9;
        float v = d.src[idx];
        __nv_bfloat16 h = __float2bfloat16(v);
        __nv_bfloat16 l = __float2bfloat16(v - __bfloat162float(h));
        size_t dd = (size_t)co * cin9 + tap * d.cin + ci;
        d.hi[dd] = h; d.lo[dd] = l;
    }
}

// bevs NCHW fp32 -> NHWC hi/lo bf16.
__global__ void actsplit_kernel(const float* __restrict__ in,
                                __nv_bfloat16* __restrict__ oh,
                                __nv_bfloat16* __restrict__ ol)
{
    __shared__ float s[32][257];
    int n = blockIdx.x, c0 = blockIdx.y * 32;
    int tid = threadIdx.x;
#pragma unroll
    for (int it = 0; it < 32; it++)
        s[it][tid] = in[((size_t)n * 256 + c0 + it) * 256 + tid];
    __syncthreads();
    int ci = tid & 31, p0 = tid >> 5;
#pragma unroll
    for (int pp = 0; pp < 32; pp++) {
        int pix = p0 + pp * 8;
        float v = s[ci][pix];
        __nv_bfloat16 h = __float2bfloat16(v);
        __nv_bfloat16 l = __float2bfloat16(v - __bfloat162float(h));
        size_t o = ((size_t)n * 256 + pix) * 256 + c0 + ci;
        oh[o] = h; ol[o] = l;
    }
}

// ---------------------------------------------------------------------------
// Implicit-GEMM conv3x3 (pad=1) + affine + ReLU, split-bf16 mma.sync.
// K-chunks of 64 (144B pitch), circular 2-stage cp.async pipeline, one
// __syncthreads per chunk.  Fragment loop: all 8 ldsm per ks, then 24 MMAs.
// ---------------------------------------------------------------------------
static constexpr int SPB = 144;

template <int CIN, int COUT, int HIN, int WIN, int STRIDE, int OUTMODE,
          int MTILE, int STAGES, int MINCTA>
__global__ void __launch_bounds__(256, MINCTA)
convMMA_kernel(const __nv_bfloat16* __restrict__ aH, const __nv_bfloat16* __restrict__ aL,
               const __nv_bfloat16* __restrict__ wH, const __nv_bfloat16* __restrict__ wL,
               const float* __restrict__ scale, const float* __restrict__ shift,
               __nv_bfloat16* __restrict__ oH, __nv_bfloat16* __restrict__ oL,
               float* __restrict__ oF)
{
    constexpr int HO   = (HIN - 1) / STRIDE + 1;
    constexpr int WO   = (WIN - 1) / STRIDE + 1;
    constexpr int MPIX = HO * WO;
    constexpr int NIMG = (MPIX >= MTILE) ? 1 : (MTILE / MPIX);
    constexpr int NT   = COUT / 128;
    constexpr int KTOT = 9 * CIN;
    constexpr int CPT  = CIN / 64;
    constexpr int NCH  = 9 * CPT;
    constexpr int MW   = MTILE / 32;
    constexpr int NW   = 8 / MW;
    constexpr int NCPW = 128 / NW;
    constexpr int NT2  = NCPW / 16;
    constexpr int STB  = (MTILE + 128) * 2 * SPB;
    constexpr int A_LO = MTILE * SPB;
    constexpr int B_HI = MTILE * 2 * SPB;
    constexpr int B_LO = B_HI + 128 * SPB;
    constexpr int RT   = (MTILE + 128) * 16;

    extern __shared__ char smem[];
    const uint32_t sb = smem_to_u32(smem);

    const int tid = threadIdx.x, wid = tid >> 5, lane = tid & 31;
    const int mt  = blockIdx.x / NT;
    const int co0 = (blockIdx.x % NT) * 128;
    const int n0  = blockIdx.y * NIMG;
    const int wm  = wid % MW;
    const int wn  = wid / MW;

    auto issue = [&](int c) {
        const uint32_t st = sb + (uint32_t)(c % STAGES) * STB;
        const int tap = c / CPT;
        const int ci0 = (c - tap * CPT) * 64;
        const int dy = tap / 3 - 1, dx = tap % 3 - 1;
#pragma unroll
        for (int i = tid; i < RT; i += 256) {
            const int row  = i >> 4;
            const int seg  = i & 7;
            const int half = (i >> 3) & 1;
            if (row < MTILE) {
                int g = mt * MTILE + row;
                int img = g / MPIX, pix = g % MPIX;
                int oh = pix / WO, ow = pix - oh * WO;
                int ih = oh * STRIDE + dy, iw = ow * STRIDE + dx;
                bool v = ((unsigned)ih < (unsigned)HIN) && ((unsigned)iw < (unsigned)WIN);
                int ihs = v ? ih : 0, iws = v ? iw : 0;
                size_t aoff = (((size_t)(n0 + img) * HIN + ihs) * WIN + iws) * CIN
                              + ci0 + seg * 8;
                uint32_t ad = st + (uint32_t)half * A_LO + (uint32_t)row * SPB + seg * 16;
                cp16(ad, (half ? aL : aH) + aoff, v);
            } else {
                int r2 = row - MTILE;
                size_t woff = (size_t)(co0 + r2) * KTOT + (size_t)c * 64 + seg * 8;
                uint32_t bd = st + B_HI + (uint32_t)half * (128 * SPB)
                              + (uint32_t)r2 * SPB + seg * 16;
                cp16(bd, (half ? wL : wH) + woff, true);
            }
        }
        CP_COMMIT();
    };

    float acc[2][NT2 * 2][4];
#pragma unroll
    for (int a = 0; a < 2; a++)
#pragma unroll
        for (int b = 0; b < NT2 * 2; b++)
#pragma unroll
            for (int c = 0; c < 4; c++) acc[a][b][c] = 0.f;

#pragma unroll
    for (int p = 0; p < STAGES - 1; p++) issue(p);

    for (int c = 0; c < NCH; c++) {
        asm volatile("cp.async.wait_group %0;" :: "n"(STAGES - 2) : "memory");
        __syncthreads();
        if (c + STAGES - 1 < NCH) issue(c + STAGES - 1);
        else CP_COMMIT();

        const uint32_t st  = sb + (uint32_t)(c % STAGES) * STB;
        const uint32_t sAh = st, sAl = st + A_LO, sBh = st + B_HI, sBl = st + B_LO;
#pragma unroll
        for (int ks = 0; ks < 4; ks++) {
            // ---- batch all fragment loads for this ks ----
            const uint32_t acol = (uint32_t)ks * 32u + ((lane >> 4) << 4);
            uint32_t ah[2][4], al2[2][4];
#pragma unroll
            for (int m2 = 0; m2 < 2; m2++) {
                uint32_t arow = (uint32_t)(wm * 32 + m2 * 16 + (lane & 15));
                ldsm_x4(ah[m2],  sAh + arow * SPB + acol);
                ldsm_x4(al2[m2], sAl + arow * SPB + acol);
            }
            uint32_t bh[NT2][4], bl4[NT2][4];
            const uint32_t bcol = (uint32_t)ks * 32u + (((lane >> 3) & 1) << 4);
#pragma unroll
            for (int nt2 = 0; nt2 < NT2; nt2++) {
                uint32_t brow = (uint32_t)(wn * NCPW + nt2 * 16 +
                                           ((lane >> 4) << 3) + (lane & 7));
                ldsm_x4(bh[nt2],  sBh + brow * SPB + bcol);
                ldsm_x4(bl4[nt2], sBl + brow * SPB + bcol);
            }
            // ---- MMAs (same per-accumulator order as R9) ----
#pragma unroll
            for (int nt2 = 0; nt2 < NT2; nt2++) {
#pragma unroll
                for (int m2 = 0; m2 < 2; m2++) {
                    mma_bf16(acc[m2][nt2 * 2],     ah[m2], bh[nt2][0], bh[nt2][1]);
                    mma_bf16(acc[m2][nt2 * 2 + 1], ah[m2], bh[nt2][2], bh[nt2][3]);
                }
#pragma unroll
                for (int m2 = 0; m2 < 2; m2++) {
                    mma_bf16(acc[m2][nt2 * 2],     ah[m2], bl4[nt2][0], bl4[nt2][1]);
                    mma_bf16(acc[m2][nt2 * 2 + 1], ah[m2], bl4[nt2][2], bl4[nt2][3]);
                    mma_bf16(acc[m2][nt2 * 2],     al2[m2], bh[nt2][0], bh[nt2][1]);
                    mma_bf16(acc[m2][nt2 * 2 + 1], al2[m2], bh[nt2][2], bh[nt2][3]);
                }
            }
        }
    }

    if (OUTMODE == 0) {
#pragma unroll
        for (int m2 = 0; m2 < 2; m2++) {
            int mA = wm * 32 + m2 * 16 + (lane >> 2);
            int gA = mt * MTILE + mA;
            int gB = gA + 8;
            size_t rowA = ((size_t)(n0 + gA / MPIX) * MPIX + gA % MPIX) * COUT;
            size_t rowB = ((size_t)(n0 + gB / MPIX) * MPIX + gB % MPIX) * COUT;
#pragma unroll
            for (int j = 0; j < NT2 * 2; j++) {
                int co = co0 + wn * NCPW + j * 8 + (lane & 3) * 2;
                float s0 = __ldg(scale + co), s1 = __ldg(scale + co + 1);
                float t0 = __ldg(shift + co), t1 = __ldg(shift + co + 1);
                float v0 = fmaxf(fmaf(acc[m2][j][0], s0, t0), 0.f);
                float v1 = fmaxf(fmaf(acc[m2][j][1], s1, t1), 0.f);
                float v2 = fmaxf(fmaf(acc[m2][j][2], s0, t0), 0.f);
                float v3 = fmaxf(fmaf(acc[m2][j][3], s1, t1), 0.f);
                __nv_bfloat16 h0 = __float2bfloat16(v0), h1 = __float2bfloat16(v1);
                __nv_bfloat16 h2 = __float2bfloat16(v2), h3 = __float2bfloat16(v3);
                __nv_bfloat16 l0 = __float2bfloat16(v0 - __bfloat162float(h0));
                __nv_bfloat16 l1 = __float2bfloat16(v1 - __bfloat162float(h1));
                __nv_bfloat16 l2 = __float2bfloat16(v2 - __bfloat162float(h2));
                __nv_bfloat16 l3 = __float2bfloat16(v3 - __bfloat162float(h3));
                *reinterpret_cast<uint32_t*>(oH + rowA + co) = pack_bf2(h0, h1);
                *reinterpret_cast<uint32_t*>(oL + rowA + co) = pack_bf2(l0, l1);
                *reinterpret_cast<uint32_t*>(oH + rowB + co) = pack_bf2(h2, h3);
                *reinterpret_cast<uint32_t*>(oL + rowB + co) = pack_bf2(l2, l3);
            }
        }
    } else {
        constexpr int OPITCH = MTILE + 4;
        float* sOut = reinterpret_cast<float*>(smem);
        __syncthreads();
#pragma unroll
        for (int m2 = 0; m2 < 2; m2++) {
#pragma unroll
            for (int j = 0; j < NT2 * 2; j++) {
                int m = wm * 32 + m2 * 16 + (lane >> 2);
                int nn = wn * NCPW + j * 8 + (lane & 3) * 2;
                sOut[(size_t)nn * OPITCH + m]           = acc[m2][j][0];
                sOut[(size_t)(nn + 1) * OPITCH + m]     = acc[m2][j][1];
                sOut[(size_t)nn * OPITCH + m + 8]       = acc[m2][j][2];
                sOut[(size_t)(nn + 1) * OPITCH + m + 8] = acc[m2][j][3];
            }
        }
        __syncthreads();
        int row = tid >> 1, half = tid & 1;
        int co = co0 + row;
        float s = __ldg(scale + co), t = __ldg(shift + co);
#pragma unroll
        for (int q = 0; q < MTILE / 8; q++) {
            int m = half * (MTILE / 2) + q * 4;
            float4 v = *reinterpret_cast<float4*>(&sOut[(size_t)row * OPITCH + m]);
            v.x = fmaxf(fmaf(v.x, s, t), 0.f);
            v.y = fmaxf(fmaf(v.y, s, t), 0.f);
            v.z = fmaxf(fmaf(v.z, s, t), 0.f);
            v.w = fmaxf(fmaf(v.w, s, t), 0.f);
            int g = mt * MTILE + m;
            int img = g / MPIX, pix = g % MPIX;
            *reinterpret_cast<float4*>(
                &oF[((size_t)(n0 + img) * COUT + co) * MPIX + pix]) = v;
        }
    }
}

// ---------------------------------------------------------------------------
// Warp-tile GEMV over TWO independent (X,W,b,Y,N) sets in one launch.
// ---------------------------------------------------------------------------
__global__ void warptile2_kernel(const float* __restrict__ X1, const float* __restrict__ W1,
                                 const float* __restrict__ B1, float* __restrict__ Y1, int N1,
                                 const float* __restrict__ X2, const float* __restrict__ W2,
                                 const float* __restrict__ B2, float* __restrict__ Y2, int N2,
                                 int M, int K, int doRelu)
{
    int gw   = (blockIdx.x * blockDim.x + threadIdx.x) >> 5;
    int lane = threadIdx.x & 31;
    int nWtot = (N1 + N2) >> 3;
    int mtile = gw / nWtot, ntile = gw - mtile * nWtot;
    if (mtile * 4 >= M) return;
    const float *X, *W, *Bb;
    float* Y;
    int N, nt;
    if (ntile < (N1 >> 3)) { X = X1; W = W1; Bb = B1; Y = Y1; N = N1; nt = ntile; }
    else { X = X2; W = W2; Bb = B2; Y = Y2; N = N2; nt = ntile - (N1 >> 3); }
    const float* x0 = X + (size_t)(mtile * 4) * K;
    const float* w0 = W + (size_t)(nt * 8) * K;
    float acc[4][8];
#pragma unroll
    for (int i = 0; i < 4; i++)
#pragma unroll
        for (int j = 0; j < 8; j++) acc[i][j] = 0.f;
    for (int k = lane; k < K; k += 32) {
        float xv[4], wv[8];
#pragma unroll
        for (int i = 0; i < 4; i++) xv[i] = x0[(size_t)i * K + k];
#pragma unroll
        for (int j = 0; j < 8; j++) wv[j] = w0[(size_t)j * K + k];
#pragma unroll
        for (int i = 0; i < 4; i++)
#pragma unroll
            for (int j = 0; j < 8; j++) acc[i][j] = fmaf(xv[i], wv[j], acc[i][j]);
    }
#pragma unroll
    for (int o = 16; o; o >>= 1)
#pragma unroll
        for (int i = 0; i < 4; i++)
#pragma unroll
            for (int j = 0; j < 8; j++)
                acc[i][j] += __shfl_xor_sync(0xffffffffu, acc[i][j], o);
    int i = lane >> 3, j = lane & 7;
    float v = acc[i][j] + Bb[nt * 8 + j];
    if (doRelu) v = fmaxf(v, 0.f);
    Y[(size_t)(mtile * 4 + i) * N + nt * 8 + j] = v;
}

__global__ void warptile_kernel(const float* __restrict__ X, const float* __restrict__ W,
                                const float* __restrict__ bias, float* __restrict__ Y,
                                int M, int N, int K, int doRelu)
{
    int gw   = (blockIdx.x * blockDim.x + threadIdx.x) >> 5;
    int lane = threadIdx.x & 31;
    int nW = N >> 3;
    int mtile = gw / nW, ntile = gw - mtile * nW;
    if (mtile * 4 >= M) return;
    const float* x0 = X + (size_t)(mtile * 4) * K;
    const float* w0 = W + (size_t)(ntile * 8) * K;
    float acc[4][8];
#pragma unroll
    for (int i = 0; i < 4; i++)
#pragma unroll
        for (int j = 0; j < 8; j++) acc[i][j] = 0.f;
    for (int k = lane; k < K; k += 32) {
        float xv[4], wv[8];
#pragma unroll
        for (int i = 0; i < 4; i++) xv[i] = x0[(size_t)i * K + k];
#pragma unroll
        for (int j = 0; j < 8; j++) wv[j] = w0[(size_t)j * K + k];
#pragma unroll
        for (int i = 0; i < 4; i++)
#pragma unroll
            for (int j = 0; j < 8; j++) acc[i][j] = fmaf(xv[i], wv[j], acc[i][j]);
    }
#pragma unroll
    for (int o = 16; o; o >>= 1)
#pragma unroll
        for (int i = 0; i < 4; i++)
#pragma unroll
            for (int j = 0; j < 8; j++)
                acc[i][j] += __shfl_xor_sync(0xffffffffu, acc[i][j], o);
    int i = lane >> 3, j = lane & 7;
    float v = acc[i][j] + bias[ntile * 8 + j];
    if (doRelu) v = fmaxf(v, 0.f);
    Y[(size_t)(mtile * 4 + i) * N + ntile * 8 + j] = v;
}

// ---------------------------------------------------------------------------
// Attention + softmax -> fuse weights; final fuse.
// ---------------------------------------------------------------------------
__global__ void attn_kernel(const float* __restrict__ keys, const float* __restrict__ qq,
                            float* __restrict__ wf)
{
    int b = blockIdx.x;
    __shared__ float sA[5][5];
    int warp = threadIdx.x >> 5, lane = threadIdx.x & 31;
    for (int e = warp; e < 25; e += 8) {
        int i = e / 5, j = e - i * 5;
        const float4* kr = (const float4*)(keys + (size_t)(i * 32 + b) * 1024);
        const float4* qr = (const float4*)(qq + (size_t)(j * 32 + b) * 1024);
        float acc = 0.f;
        for (int k = lane; k < 256; k += 32) {
            float4 a = kr[k], c = qr[k];
            acc += a.x * c.x + a.y * c.y + a.z * c.z + a.w * c.w;
        }
#pragma unroll
        for (int o = 16; o; o >>= 1) acc += __shfl_xor_sync(0xffffffffu, acc, o);
        if (lane == 0) sA[i][j] = acc;
    }
    __syncthreads();
    if (threadIdx.x == 0) {
        float w[5] = {0.f, 0.f, 0.f, 0.f, 0.f};
        for (int j = 0; j < 5; j++) {
            float dd[4], mx = -1e30f;
            for (int r = 0; r < 4; r++) {
                dd[r] = (j > r) ? sA[r][j] : sA[r + 1][j];
                mx = fmaxf(mx, dd[r]);
            }
            float s = 0.f;
            for (int r = 0; r < 4; r++) { dd[r] = expf(dd[r] - mx); s += dd[r]; }
            float inv = 1.f / s;
            for (int r = 0; r < 4; r++) {
                int i = (j > r) ? r : r + 1;
                w[i] += dd[r] * inv;
            }
        }
        for (int i = 0; i < 5; i++) wf[b * 5 + i] = w[i] * 0.2f;
    }
}

__global__ void fuse_kernel(const float* __restrict__ bevs, const float* __restrict__ wf,
                            float* __restrict__ out)
{
    const int CHW = 256 * 16 * 16;
    int idx = blockIdx.x * blockDim.x + threadIdx.x;
    if (idx >= 32 * CHW) return;
    int b   = idx / CHW;
    int chw = idx - b * CHW;
    const float* base = bevs + ((size_t)b * 5) * CHW + chw;
    float acc = 0.f;
#pragma unroll
    for (int k = 0; k < 5; k++) acc += wf[b * 5 + k] * base[(size_t)k * CHW];
    out[idx] = acc;
}

// ---------------------------------------------------------------------------
extern "C" void kernel_launch(void* const* d_in, const int* in_sizes, int n_in,
                              void* d_out, int out_size)
{
    (void)in_sizes; (void)n_in; (void)out_size;
    const float* bevs = (const float*)d_in[0];
    const float *cw[5], *cs[5], *ct[5];
    for (int i = 0; i < 5; i++) {
        cw[i] = (const float*)d_in[1 + 3 * i];
        cs[i] = (const float*)d_in[2 + 3 * i];
        ct[i] = (const float*)d_in[3 + 3 * i];
    }
    const float* kw1 = (const float*)d_in[16]; const float* kb1 = (const float*)d_in[17];
    const float* kw2 = (const float*)d_in[18]; const float* kb2 = (const float*)d_in[19];
    const float* kw3 = (const float*)d_in[20]; const float* kb3 = (const float*)d_in[21];
    const float* qw1 = (const float*)d_in[22]; const float* qb1 = (const float*)d_in[23];
    const float* qw2 = (const float*)d_in[24]; const float* qb2 = (const float*)d_in[25];
    const float* qw3 = (const float*)d_in[26]; const float* qb3 = (const float*)d_in[27];
    const float* aw  = (const float*)d_in[28]; const float* ab  = (const float*)d_in[29];
    float* out = (float*)d_out;

    __nv_bfloat16 *a0h, *a0l, *b1h, *b1l, *b2h, *b2l, *b3h, *b3l, *b4h, *b4l;
    cudaGetSymbolAddress((void**)&a0h, g_a0h); cudaGetSymbolAddress((void**)&a0l, g_a0l);
    cudaGetSymbolAddress((void**)&b1h, g_b1h); cudaGetSymbolAddress((void**)&b1l, g_b1l);
    cudaGetSymbolAddress((void**)&b2h, g_b2h); cudaGetSymbolAddress((void**)&b2l, g_b2l);
    cudaGetSymbolAddress((void**)&b3h, g_b3h); cudaGetSymbolAddress((void**)&b3l, g_b3l);
    cudaGetSymbolAddress((void**)&b4h, g_b4h); cudaGetSymbolAddress((void**)&b4l, g_b4l);
    float *feat, *m1k, *m1q, *m2k, *m2q, *keys, *qrys, *qq, *wf;
    cudaGetSymbolAddress((void**)&feat, g_feat);
    cudaGetSymbolAddress((void**)&m1k, g_m1k);
    cudaGetSymbolAddress((void**)&m1q, g_m1q);
    cudaGetSymbolAddress((void**)&m2k, g_m2k);
    cudaGetSymbolAddress((void**)&m2q, g_m2q);
    cudaGetSymbolAddress((void**)&keys, g_keys);
    cudaGetSymbolAddress((void**)&qrys, g_qrys);
    cudaGetSymbolAddress((void**)&qq, g_qq);
    cudaGetSymbolAddress((void**)&wf, g_wf);
    __nv_bfloat16 *w1h, *w1l, *w2h, *w2l, *w3h, *w3l, *w4h, *w4l, *w5h, *w5l;
    cudaGetSymbolAddress((void**)&w1h, g_w1h); cudaGetSymbolAddress((void**)&w1l, g_w1l);
    cudaGetSymbolAddress((void**)&w2h, g_w2h); cudaGetSymbolAddress((void**)&w2l, g_w2l);
    cudaGetSymbolAddress((void**)&w3h, g_w3h); cudaGetSymbolAddress((void**)&w3l, g_w3l);
    cudaGetSymbolAddress((void**)&w4h, g_w4h); cudaGetSymbolAddress((void**)&w4l, g_w4l);
    cudaGetSymbolAddress((void**)&w5h, g_w5h); cudaGetSymbolAddress((void**)&w5l, g_w5l);

    constexpr int SMEM_S = 2 * 55296;   // 110592, 2 CTAs/SM

    cudaFuncSetAttribute(convMMA_kernel<256, 512, 16, 16, 1, 0, 64, 2, 2>,
                         cudaFuncAttributeMaxDynamicSharedMemorySize, SMEM_S);
    cudaFuncSetAttribute(convMMA_kernel<512, 256, 16, 16, 1, 0, 64, 2, 2>,
                         cudaFuncAttributeMaxDynamicSharedMemorySize, SMEM_S);
    cudaFuncSetAttribute(convMMA_kernel<256, 256, 16, 16, 2, 0, 64, 2, 2>,
                         cudaFuncAttributeMaxDynamicSharedMemorySize, SMEM_S);
    cudaFuncSetAttribute(convMMA_kernel<256, 256, 8, 8, 1, 0, 64, 2, 2>,
                         cudaFuncAttributeMaxDynamicSharedMemorySize, SMEM_S);
    cudaFuncSetAttribute(convMMA_kernel<256, 256, 8, 8, 2, 1, 64, 2, 2>,
                         cudaFuncAttributeMaxDynamicSharedMemorySize, SMEM_S);

    // ---- launch 0: all weight preps in one kernel ----
    {
        int t1 = 512 * 2304, t2 = 256 * 4608, t3 = 256 * 2304;
        WPrepDesc d0 = {cw[0], w1h, w1l, 256, t1, 0};
        WPrepDesc d1 = {cw[1], w2h, w2l, 512, t2, t1};
        WPrepDesc d2 = {cw[2], w3h, w3l, 256, t3, t1 + t2};
        WPrepDesc d3 = {cw[3], w4h, w4l, 256, t3, t1 + t2 + t3};
        WPrepDesc d4 = {cw[4], w5h, w5l, 256, t3, t1 + t2 + 2 * t3};
        int grand = t1 + t2 + 3 * t3;
        wprep_all_kernel<<<1184, 256>>>(d0, d1, d2, d3, d4, grand);
    }
    // ---- launch 1: bevs split ----
    actsplit_kernel<<<dim3(160, 8), 256>>>(bevs, a0h, a0l);

    // ---- launches 2..6: conv stack, all MTILE=64 @ 2 CTAs/SM ----
    convMMA_kernel<256, 512, 16, 16, 1, 0, 64, 2, 2><<<dim3(16, 160), 256, SMEM_S>>>(
        a0h, a0l, w1h, w1l, cs[0], ct[0], b1h, b1l, nullptr);
    convMMA_kernel<512, 256, 16, 16, 1, 0, 64, 2, 2><<<dim3(8, 160), 256, SMEM_S>>>(
        b1h, b1l, w2h, w2l, cs[1], ct[1], b2h, b2l, nullptr);
    convMMA_kernel<256, 256, 16, 16, 2, 0, 64, 2, 2><<<dim3(2, 160), 256, SMEM_S>>>(
        b2h, b2l, w3h, w3l, cs[2], ct[2], b3h, b3l, nullptr);
    convMMA_kernel<256, 256, 8, 8, 1, 0, 64, 2, 2><<<dim3(2, 160), 256, SMEM_S>>>(
        b3h, b3l, w4h, w4l, cs[3], ct[3], b4h, b4l, nullptr);
    convMMA_kernel<256, 256, 8, 8, 2, 1, 64, 2, 2><<<dim3(2, 40), 256, SMEM_S>>>(
        b4h, b4l, w5h, w5l, cs[4], ct[4], nullptr, nullptr, feat);

    // ---- fused k/q tail ----
    auto wt2 = [&](const float* X1, const float* W1, const float* B1, float* Y1, int N1,
                   const float* X2, const float* W2, const float* B2, float* Y2, int N2,
                   int M, int K, int relu) {
        int warps = (M / 4) * ((N1 + N2) / 8);
        warptile2_kernel<<<(warps + 7) / 8, 256>>>(X1, W1, B1, Y1, N1,
                                                   X2, W2, B2, Y2, N2, M, K, relu);
    };
    wt2(feat, kw1, kb1, m1k, 256, feat, qw1, qb1, m1q, 256, 160, 4096, 1);
    wt2(m1k, kw2, kb2, m2k, 128, m1q, qw2, qb2, m2q, 128, 160, 256, 1);
    wt2(m2k, kw3, kb3, keys, 1024, m2q, qw3, qb3, qrys, 32, 160, 128, 0);
    {
        int warps = (160 / 4) * (1024 / 8);
        warptile_kernel<<<(warps + 7) / 8, 256>>>(qrys, aw, ab, qq, 160, 1024, 32, 0);
    }

    attn_kernel<<<32, 256>>>(keys, qq, wf);
    fuse_kernel<<<(32 * 256 * 16 * 16 + 255) / 256, 256>>>(bevs, wf, out);
}

// round 15
// speedup vs baseline: 1.5132x; 1.0020x over previous
#include <cuda_runtime.h>
#include <cuda_bf16.h>
#include <cstdint>
#include <cstddef>

// ===========================================================================
// Who2com forward — split-bf16 mma.sync implicit-GEMM convs.
// R12: single change vs R11 — MMA issue order grouped into three term-passes
// (ah*bh x8, ah*bl x8, al*bh x8) so same-accumulator reuse distance is 8
// instructions (clears HMMA accumulator RAW latency). Per-accumulator
// operand order unchanged -> bitwise-identical numerics.
// ===========================================================================

__device__ __forceinline__ uint32_t smem_to_u32(const void* p) {
    uint32_t a;
    asm("{ .reg .u64 t; cvta.to.shared.u64 t, %1; cvt.u32.u64 %0, t; }"
        : "=r"(a) : "l"(p));
    return a;
}
__device__ __forceinline__ void ldsm_x4(uint32_t (&r)[4], uint32_t addr) {
    asm volatile("ldmatrix.sync.aligned.m8n8.x4.shared.b16 {%0,%1,%2,%3}, [%4];"
                 : "=r"(r[0]), "=r"(r[1]), "=r"(r[2]), "=r"(r[3]) : "r"(addr));
}
__device__ __forceinline__ void mma_bf16(float (&d)[4], const uint32_t (&a)[4],
                                         uint32_t b0, uint32_t b1) {
    asm volatile(
        "mma.sync.aligned.m16n8k16.row.col.f32.bf16.bf16.f32 "
        "{%0,%1,%2,%3}, {%4,%5,%6,%7}, {%8,%9}, {%0,%1,%2,%3};"
        : "+f"(d[0]), "+f"(d[1]), "+f"(d[2]), "+f"(d[3])
        : "r"(a[0]), "r"(a[1]), "r"(a[2]), "r"(a[3]), "r"(b0), "r"(b1));
}
__device__ __forceinline__ uint32_t pack_bf2(__nv_bfloat16 a, __nv_bfloat16 b) {
    __nv_bfloat162 t = __halves2bfloat162(a, b);
    return *reinterpret_cast<uint32_t*>(&t);
}
__device__ __forceinline__ void cp16(uint32_t dst, const void* src, bool v) {
    asm volatile("cp.async.cg.shared.global [%0], [%1], 16, %2;"
                 :: "r"(dst), "l"(src), "r"(v ? 16u : 0u) : "memory");
}
#define CP_COMMIT() asm volatile("cp.async.commit_group;" ::: "memory")

// ---------------------------------------------------------------------------
// Scratch
// ---------------------------------------------------------------------------
__device__ __align__(16) __nv_bfloat16 g_a0h[(size_t)160 * 256 * 256];
__device__ __align__(16) __nv_bfloat16 g_a0l[(size_t)160 * 256 * 256];
__device__ __align__(16) __nv_bfloat16 g_b1h[(size_t)160 * 256 * 512];
__device__ __align__(16) __nv_bfloat16 g_b1l[(size_t)160 * 256 * 512];
__device__ __align__(16) __nv_bfloat16 g_b2h[(size_t)160 * 256 * 256];
__device__ __align__(16) __nv_bfloat16 g_b2l[(size_t)160 * 256 * 256];
__device__ __align__(16) __nv_bfloat16 g_b3h[(size_t)160 * 64 * 256];
__device__ __align__(16) __nv_bfloat16 g_b3l[(size_t)160 * 64 * 256];
__device__ __align__(16) __nv_bfloat16 g_b4h[(size_t)160 * 64 * 256];
__device__ __align__(16) __nv_bfloat16 g_b4l[(size_t)160 * 64 * 256];
__device__ float g_feat[(size_t)160 * 4096];
__device__ float g_m1k[160 * 256], g_m1q[160 * 256];
__device__ float g_m2k[160 * 128], g_m2q[160 * 128];
__device__ float g_keys[160 * 1024];
__device__ float g_qrys[160 * 32];
__device__ float g_qq[160 * 1024];
__device__ float g_wf[32 * 5];
__device__ __align__(16) __nv_bfloat16 g_w1h[512 * 2304], g_w1l[512 * 2304];
__device__ __align__(16) __nv_bfloat16 g_w2h[256 * 4608], g_w2l[256 * 4608];
__device__ __align__(16) __nv_bfloat16 g_w3h[256 * 2304], g_w3l[256 * 2304];
__device__ __align__(16) __nv_bfloat16 g_w4h[256 * 2304], g_w4l[256 * 2304];
__device__ __align__(16) __nv_bfloat16 g_w5h[256 * 2304], g_w5l[256 * 2304];

// ---------------------------------------------------------------------------
// Merged weight prep: all 5 conv layers in one launch.
// ---------------------------------------------------------------------------
struct WPrepDesc {
    const float* src;
    __nv_bfloat16* hi;
    __nv_bfloat16* lo;
    int cin;
    int total;
    int base;
};

__global__ void wprep_all_kernel(WPrepDesc d0, WPrepDesc d1, WPrepDesc d2,
                                 WPrepDesc d3, WPrepDesc d4, int grand)
{
    WPrepDesc ds[5] = {d0, d1, d2, d3, d4};
    for (int g = blockIdx.x * blockDim.x + threadIdx.x; g < grand;
         g += gridDim.x * blockDim.x) {
        int li = 0;
#pragma unroll
        for (int t = 1; t < 5; t++)
            if (g >= ds[t].base) li = t;
        const WPrepDesc& d = ds[li];
        int idx = g - d.base;
        int cin9 = d.cin * 9;
        int co = idx / cin9;
        int rem = idx - co * cin9;
        int ci = rem / 9, tap = rem - ci * 9;
        float v = d.src[idx];
        __nv_bfloat16 h = __float2bfloat16(v);
        __nv_bfloat16 l = __float2bfloat16(v - __bfloat162float(h));
        size_t dd = (size_t)co * cin9 + tap * d.cin + ci;
        d.hi[dd] = h; d.lo[dd] = l;
    }
}

// bevs NCHW fp32 -> NHWC hi/lo bf16.
__global__ void actsplit_kernel(const float* __restrict__ in,
                                __nv_bfloat16* __restrict__ oh,
                                __nv_bfloat16* __restrict__ ol)
{
    __shared__ float s[32][257];
    int n = blockIdx.x, c0 = blockIdx.y * 32;
    int tid = threadIdx.x;
#pragma unroll
    for (int it = 0; it < 32; it++)
        s[it][tid] = in[((size_t)n * 256 + c0 + it) * 256 + tid];
    __syncthreads();
    int ci = tid & 31, p0 = tid >> 5;
#pragma unroll
    for (int pp = 0; pp < 32; pp++) {
        int pix = p0 + pp * 8;
        float v = s[ci][pix];
        __nv_bfloat16 h = __float2bfloat16(v);
        __nv_bfloat16 l = __float2bfloat16(v - __bfloat162float(h));
        size_t o = ((size_t)n * 256 + pix) * 256 + c0 + ci;
        oh[o] = h; ol[o] = l;
    }
}

// ---------------------------------------------------------------------------
// Implicit-GEMM conv3x3 (pad=1) + affine + ReLU, split-bf16 mma.sync.
// K-chunks of 64 (144B pitch), circular 2-stage cp.async pipeline, one
// __syncthreads per chunk.  MMAs issued in three term-passes per ks.
// ---------------------------------------------------------------------------
static constexpr int SPB = 144;

template <int CIN, int COUT, int HIN, int WIN, int STRIDE, int OUTMODE,
          int MTILE, int STAGES, int MINCTA>
__global__ void __launch_bounds__(256, MINCTA)
convMMA_kernel(const __nv_bfloat16* __restrict__ aH, const __nv_bfloat16* __restrict__ aL,
               const __nv_bfloat16* __restrict__ wH, const __nv_bfloat16* __restrict__ wL,
               const float* __restrict__ scale, const float* __restrict__ shift,
               __nv_bfloat16* __restrict__ oH, __nv_bfloat16* __restrict__ oL,
               float* __restrict__ oF)
{
    constexpr int HO   = (HIN - 1) / STRIDE + 1;
    constexpr int WO   = (WIN - 1) / STRIDE + 1;
    constexpr int MPIX = HO * WO;
    constexpr int NIMG = (MPIX >= MTILE) ? 1 : (MTILE / MPIX);
    constexpr int NT   = COUT / 128;
    constexpr int KTOT = 9 * CIN;
    constexpr int CPT  = CIN / 64;
    constexpr int NCH  = 9 * CPT;
    constexpr int MW   = MTILE / 32;
    constexpr int NW   = 8 / MW;
    constexpr int NCPW = 128 / NW;
    constexpr int NT2  = NCPW / 16;
    constexpr int STB  = (MTILE + 128) * 2 * SPB;
    constexpr int A_LO = MTILE * SPB;
    constexpr int B_HI = MTILE * 2 * SPB;
    constexpr int B_LO = B_HI + 128 * SPB;
    constexpr int RT   = (MTILE + 128) * 16;

    extern __shared__ char smem[];
    const uint32_t sb = smem_to_u32(smem);

    const int tid = threadIdx.x, wid = tid >> 5, lane = tid & 31;
    const int mt  = blockIdx.x / NT;
    const int co0 = (blockIdx.x % NT) * 128;
    const int n0  = blockIdx.y * NIMG;
    const int wm  = wid % MW;
    const int wn  = wid / MW;

    auto issue = [&](int c) {
        const uint32_t st = sb + (uint32_t)(c % STAGES) * STB;
        const int tap = c / CPT;
        const int ci0 = (c - tap * CPT) * 64;
        const int dy = tap / 3 - 1, dx = tap % 3 - 1;
#pragma unroll
        for (int i = tid; i < RT; i += 256) {
            const int row  = i >> 4;
            const int seg  = i & 7;
            const int half = (i >> 3) & 1;
            if (row < MTILE) {
                int g = mt * MTILE + row;
                int img = g / MPIX, pix = g % MPIX;
                int oh = pix / WO, ow = pix - oh * WO;
                int ih = oh * STRIDE + dy, iw = ow * STRIDE + dx;
                bool v = ((unsigned)ih < (unsigned)HIN) && ((unsigned)iw < (unsigned)WIN);
                int ihs = v ? ih : 0, iws = v ? iw : 0;
                size_t aoff = (((size_t)(n0 + img) * HIN + ihs) * WIN + iws) * CIN
                              + ci0 + seg * 8;
                uint32_t ad = st + (uint32_t)half * A_LO + (uint32_t)row * SPB + seg * 16;
                cp16(ad, (half ? aL : aH) + aoff, v);
            } else {
                int r2 = row - MTILE;
                size_t woff = (size_t)(co0 + r2) * KTOT + (size_t)c * 64 + seg * 8;
                uint32_t bd = st + B_HI + (uint32_t)half * (128 * SPB)
                              + (uint32_t)r2 * SPB + seg * 16;
                cp16(bd, (half ? wL : wH) + woff, true);
            }
        }
        CP_COMMIT();
    };

    float acc[2][NT2 * 2][4];
#pragma unroll
    for (int a = 0; a < 2; a++)
#pragma unroll
        for (int b = 0; b < NT2 * 2; b++)
#pragma unroll
            for (int c = 0; c < 4; c++) acc[a][b][c] = 0.f;

#pragma unroll
    for (int p = 0; p < STAGES - 1; p++) issue(p);

    for (int c = 0; c < NCH; c++) {
        asm volatile("cp.async.wait_group %0;" :: "n"(STAGES - 2) : "memory");
        __syncthreads();
        if (c + STAGES - 1 < NCH) issue(c + STAGES - 1);
        else CP_COMMIT();

        const uint32_t st  = sb + (uint32_t)(c % STAGES) * STB;
        const uint32_t sAh = st, sAl = st + A_LO, sBh = st + B_HI, sBl = st + B_LO;
#pragma unroll
        for (int ks = 0; ks < 4; ks++) {
            // ---- batch all fragment loads for this ks ----
            const uint32_t acol = (uint32_t)ks * 32u + ((lane >> 4) << 4);
            uint32_t ah[2][4], al2[2][4];
#pragma unroll
            for (int m2 = 0; m2 < 2; m2++) {
                uint32_t arow = (uint32_t)(wm * 32 + m2 * 16 + (lane & 15));
                ldsm_x4(ah[m2],  sAh + arow * SPB + acol);
                ldsm_x4(al2[m2], sAl + arow * SPB + acol);
            }
            uint32_t bh[NT2][4], bl4[NT2][4];
            const uint32_t bcol = (uint32_t)ks * 32u + (((lane >> 3) & 1) << 4);
#pragma unroll
            for (int nt2 = 0; nt2 < NT2; nt2++) {
                uint32_t brow = (uint32_t)(wn * NCPW + nt2 * 16 +
                                           ((lane >> 4) << 3) + (lane & 7));
                ldsm_x4(bh[nt2],  sBh + brow * SPB + bcol);
                ldsm_x4(bl4[nt2], sBl + brow * SPB + bcol);
            }
            // ---- MMAs in three term-passes: same-acc distance = 8 ----
            // pass 1: ah * bh
#pragma unroll
            for (int nt2 = 0; nt2 < NT2; nt2++)
#pragma unroll
                for (int m2 = 0; m2 < 2; m2++) {
                    mma_bf16(acc[m2][nt2 * 2],     ah[m2], bh[nt2][0], bh[nt2][1]);
                    mma_bf16(acc[m2][nt2 * 2 + 1], ah[m2], bh[nt2][2], bh[nt2][3]);
                }
            // pass 2: ah * bl
#pragma unroll
            for (int nt2 = 0; nt2 < NT2; nt2++)
#pragma unroll
                for (int m2 = 0; m2 < 2; m2++) {
                    mma_bf16(acc[m2][nt2 * 2],     ah[m2], bl4[nt2][0], bl4[nt2][1]);
                    mma_bf16(acc[m2][nt2 * 2 + 1], ah[m2], bl4[nt2][2], bl4[nt2][3]);
                }
            // pass 3: al * bh
#pragma unroll
            for (int nt2 = 0; nt2 < NT2; nt2++)
#pragma unroll
                for (int m2 = 0; m2 < 2; m2++) {
                    mma_bf16(acc[m2][nt2 * 2],     al2[m2], bh[nt2][0], bh[nt2][1]);
                    mma_bf16(acc[m2][nt2 * 2 + 1], al2[m2], bh[nt2][2], bh[nt2][3]);
                }
        }
    }

    if (OUTMODE == 0) {
#pragma unroll
        for (int m2 = 0; m2 < 2; m2++) {
            int mA = wm * 32 + m2 * 16 + (lane >> 2);
            int gA = mt * MTILE + mA;
            int gB = gA + 8;
            size_t rowA = ((size_t)(n0 + gA / MPIX) * MPIX + gA % MPIX) * COUT;
            size_t rowB = ((size_t)(n0 + gB / MPIX) * MPIX + gB % MPIX) * COUT;
#pragma unroll
            for (int j = 0; j < NT2 * 2; j++) {
                int co = co0 + wn * NCPW + j * 8 + (lane & 3) * 2;
                float s0 = __ldg(scale + co), s1 = __ldg(scale + co + 1);
                float t0 = __ldg(shift + co), t1 = __ldg(shift + co + 1);
                float v0 = fmaxf(fmaf(acc[m2][j][0], s0, t0), 0.f);
                float v1 = fmaxf(fmaf(acc[m2][j][1], s1, t1), 0.f);
                float v2 = fmaxf(fmaf(acc[m2][j][2], s0, t0), 0.f);
                float v3 = fmaxf(fmaf(acc[m2][j][3], s1, t1), 0.f);
                __nv_bfloat16 h0 = __float2bfloat16(v0), h1 = __float2bfloat16(v1);
                __nv_bfloat16 h2 = __float2bfloat16(v2), h3 = __float2bfloat16(v3);
                __nv_bfloat16 l0 = __float2bfloat16(v0 - __bfloat162float(h0));
                __nv_bfloat16 l1 = __float2bfloat16(v1 - __bfloat162float(h1));
                __nv_bfloat16 l2 = __float2bfloat16(v2 - __bfloat162float(h2));
                __nv_bfloat16 l3 = __float2bfloat16(v3 - __bfloat162float(h3));
                *reinterpret_cast<uint32_t*>(oH + rowA + co) = pack_bf2(h0, h1);
                *reinterpret_cast<uint32_t*>(oL + rowA + co) = pack_bf2(l0, l1);
                *reinterpret_cast<uint32_t*>(oH + rowB + co) = pack_bf2(h2, h3);
                *reinterpret_cast<uint32_t*>(oL + rowB + co) = pack_bf2(l2, l3);
            }
        }
    } else {
        constexpr int OPITCH = MTILE + 4;
        float* sOut = reinterpret_cast<float*>(smem);
        __syncthreads();
#pragma unroll
        for (int m2 = 0; m2 < 2; m2++) {
#pragma unroll
            for (int j = 0; j < NT2 * 2; j++) {
                int m = wm * 32 + m2 * 16 + (lane >> 2);
                int nn = wn * NCPW + j * 8 + (lane & 3) * 2;
                sOut[(size_t)nn * OPITCH + m]           = acc[m2][j][0];
                sOut[(size_t)(nn + 1) * OPITCH + m]     = acc[m2][j][1];
                sOut[(size_t)nn * OPITCH + m + 8]       = acc[m2][j][2];
                sOut[(size_t)(nn + 1) * OPITCH + m + 8] = acc[m2][j][3];
            }
        }
        __syncthreads();
        int row = tid >> 1, half = tid & 1;
        int co = co0 + row;
        float s = __ldg(scale + co), t = __ldg(shift + co);
#pragma unroll
        for (int q = 0; q < MTILE / 8; q++) {
            int m = half * (MTILE / 2) + q * 4;
            float4 v = *reinterpret_cast<float4*>(&sOut[(size_t)row * OPITCH + m]);
            v.x = fmaxf(fmaf(v.x, s, t), 0.f);
            v.y = fmaxf(fmaf(v.y, s, t), 0.f);
            v.z = fmaxf(fmaf(v.z, s, t), 0.f);
            v.w = fmaxf(fmaf(v.w, s, t), 0.f);
            int g = mt * MTILE + m;
            int img = g / MPIX, pix = g % MPIX;
            *reinterpret_cast<float4*>(
                &oF[((size_t)(n0 + img) * COUT + co) * MPIX + pix]) = v;
        }
    }
}

// ---------------------------------------------------------------------------
// Warp-tile GEMV over TWO independent (X,W,b,Y,N) sets in one launch.
// ---------------------------------------------------------------------------
__global__ void warptile2_kernel(const float* __restrict__ X1, const float* __restrict__ W1,
                                 const float* __restrict__ B1, float* __restrict__ Y1, int N1,
                                 const float* __restrict__ X2, const float* __restrict__ W2,
                                 const float* __restrict__ B2, float* __restrict__ Y2, int N2,
                                 int M, int K, int doRelu)
{
    int gw   = (blockIdx.x * blockDim.x + threadIdx.x) >> 5;
    int lane = threadIdx.x & 31;
    int nWtot = (N1 + N2) >> 3;
    int mtile = gw / nWtot, ntile = gw - mtile * nWtot;
    if (mtile * 4 >= M) return;
    const float *X, *W, *Bb;
    float* Y;
    int N, nt;
    if (ntile < (N1 >> 3)) { X = X1; W = W1; Bb = B1; Y = Y1; N = N1; nt = ntile; }
    else { X = X2; W = W2; Bb = B2; Y = Y2; N = N2; nt = ntile - (N1 >> 3); }
    const float* x0 = X + (size_t)(mtile * 4) * K;
    const float* w0 = W + (size_t)(nt * 8) * K;
    float acc[4][8];
#pragma unroll
    for (int i = 0; i < 4; i++)
#pragma unroll
        for (int j = 0; j < 8; j++) acc[i][j] = 0.f;
    for (int k = lane; k < K; k += 32) {
        float xv[4], wv[8];
#pragma unroll
        for (int i = 0; i < 4; i++) xv[i] = x0[(size_t)i * K + k];
#pragma unroll
        for (int j = 0; j < 8; j++) wv[j] = w0[(size_t)j * K + k];
#pragma unroll
        for (int i = 0; i < 4; i++)
#pragma unroll
            for (int j = 0; j < 8; j++) acc[i][j] = fmaf(xv[i], wv[j], acc[i][j]);
    }
#pragma unroll
    for (int o = 16; o; o >>= 1)
#pragma unroll
        for (int i = 0; i < 4; i++)
#pragma unroll
            for (int j = 0; j < 8; j++)
                acc[i][j] += __shfl_xor_sync(0xffffffffu, acc[i][j], o);
    int i = lane >> 3, j = lane & 7;
    float v = acc[i][j] + Bb[nt * 8 + j];
    if (doRelu) v = fmaxf(v, 0.f);
    Y[(size_t)(mtile * 4 + i) * N + nt * 8 + j] = v;
}

__global__ void warptile_kernel(const float* __restrict__ X, const float* __restrict__ W,
                                const float* __restrict__ bias, float* __restrict__ Y,
                                int M, int N, int K, int doRelu)
{
    int gw   = (blockIdx.x * blockDim.x + threadIdx.x) >> 5;
    int lane = threadIdx.x & 31;
    int nW = N >> 3;
    int mtile = gw / nW, ntile = gw - mtile * nW;
    if (mtile * 4 >= M) return;
    const float* x0 = X + (size_t)(mtile * 4) * K;
    const float* w0 = W + (size_t)(ntile * 8) * K;
    float acc[4][8];
#pragma unroll
    for (int i = 0; i < 4; i++)
#pragma unroll
        for (int j = 0; j < 8; j++) acc[i][j] = 0.f;
    for (int k = lane; k < K; k += 32) {
        float xv[4], wv[8];
#pragma unroll
        for (int i = 0; i < 4; i++) xv[i] = x0[(size_t)i * K + k];
#pragma unroll
        for (int j = 0; j < 8; j++) wv[j] = w0[(size_t)j * K + k];
#pragma unroll
        for (int i = 0; i < 4; i++)
#pragma unroll
            for (int j = 0; j < 8; j++) acc[i][j] = fmaf(xv[i], wv[j], acc[i][j]);
    }
#pragma unroll
    for (int o = 16; o; o >>= 1)
#pragma unroll
        for (int i = 0; i < 4; i++)
#pragma unroll
            for (int j = 0; j < 8; j++)
                acc[i][j] += __shfl_xor_sync(0xffffffffu, acc[i][j], o);
    int i = lane >> 3, j = lane & 7;
    float v = acc[i][j] + bias[ntile * 8 + j];
    if (doRelu) v = fmaxf(v, 0.f);
    Y[(size_t)(mtile * 4 + i) * N + ntile * 8 + j] = v;
}

// ---------------------------------------------------------------------------
// Attention + softmax -> fuse weights; final fuse.
// ---------------------------------------------------------------------------
__global__ void attn_kernel(const float* __restrict__ keys, const float* __restrict__ qq,
                            float* __restrict__ wf)
{
    int b = blockIdx.x;
    __shared__ float sA[5][5];
    int warp = threadIdx.x >> 5, lane = threadIdx.x & 31;
    for (int e = warp; e < 25; e += 8) {
        int i = e / 5, j = e - i * 5;
        const float4* kr = (const float4*)(keys + (size_t)(i * 32 + b) * 1024);
        const float4* qr = (const float4*)(qq + (size_t)(j * 32 + b) * 1024);
        float acc = 0.f;
        for (int k = lane; k < 256; k += 32) {
            float4 a = kr[k], c = qr[k];
            acc += a.x * c.x + a.y * c.y + a.z * c.z + a.w * c.w;
        }
#pragma unroll
        for (int o = 16; o; o >>= 1) acc += __shfl_xor_sync(0xffffffffu, acc, o);
        if (lane == 0) sA[i][j] = acc;
    }
    __syncthreads();
    if (threadIdx.x == 0) {
        float w[5] = {0.f, 0.f, 0.f, 0.f, 0.f};
        for (int j = 0; j < 5; j++) {
            float dd[4], mx = -1e30f;
            for (int r = 0; r < 4; r++) {
                dd[r] = (j > r) ? sA[r][j] : sA[r + 1][j];
                mx = fmaxf(mx, dd[r]);
            }
            float s = 0.f;
            for (int r = 0; r < 4; r++) { dd[r] = expf(dd[r] - mx); s += dd[r]; }
            float inv = 1.f / s;
            for (int r = 0; r < 4; r++) {
                int i = (j > r) ? r : r + 1;
                w[i] += dd[r] * inv;
            }
        }
        for (int i = 0; i < 5; i++) wf[b * 5 + i] = w[i] * 0.2f;
    }
}

__global__ void fuse_kernel(const float* __restrict__ bevs, const float* __restrict__ wf,
                            float* __restrict__ out)
{
    const int CHW = 256 * 16 * 16;
    int idx = blockIdx.x * blockDim.x + threadIdx.x;
    if (idx >= 32 * CHW) return;
    int b   = idx / CHW;
    int chw = idx - b * CHW;
    const float* base = bevs + ((size_t)b * 5) * CHW + chw;
    float acc = 0.f;
#pragma unroll
    for (int k = 0; k < 5; k++) acc += wf[b * 5 + k] * base[(size_t)k * CHW];
    out[idx] = acc;
}

// ---------------------------------------------------------------------------
extern "C" void kernel_launch(void* const* d_in, const int* in_sizes, int n_in,
                              void* d_out, int out_size)
{
    (void)in_sizes; (void)n_in; (void)out_size;
    const float* bevs = (const float*)d_in[0];
    const float *cw[5], *cs[5], *ct[5];
    for (int i = 0; i < 5; i++) {
        cw[i] = (const float*)d_in[1 + 3 * i];
        cs[i] = (const float*)d_in[2 + 3 * i];
        ct[i] = (const float*)d_in[3 + 3 * i];
    }
    const float* kw1 = (const float*)d_in[16]; const float* kb1 = (const float*)d_in[17];
    const float* kw2 = (const float*)d_in[18]; const float* kb2 = (const float*)d_in[19];
    const float* kw3 = (const float*)d_in[20]; const float* kb3 = (const float*)d_in[21];
    const float* qw1 = (const float*)d_in[22]; const float* qb1 = (const float*)d_in[23];
    const float* qw2 = (const float*)d_in[24]; const float* qb2 = (const float*)d_in[25];
    const float* qw3 = (const float*)d_in[26]; const float* qb3 = (const float*)d_in[27];
    const float* aw  = (const float*)d_in[28]; const float* ab  = (const float*)d_in[29];
    float* out = (float*)d_out;

    __nv_bfloat16 *a0h, *a0l, *b1h, *b1l, *b2h, *b2l, *b3h, *b3l, *b4h, *b4l;
    cudaGetSymbolAddress((void**)&a0h, g_a0h); cudaGetSymbolAddress((void**)&a0l, g_a0l);
    cudaGetSymbolAddress((void**)&b1h, g_b1h); cudaGetSymbolAddress((void**)&b1l, g_b1l);
    cudaGetSymbolAddress((void**)&b2h, g_b2h); cudaGetSymbolAddress((void**)&b2l, g_b2l);
    cudaGetSymbolAddress((void**)&b3h, g_b3h); cudaGetSymbolAddress((void**)&b3l, g_b3l);
    cudaGetSymbolAddress((void**)&b4h, g_b4h); cudaGetSymbolAddress((void**)&b4l, g_b4l);
    float *feat, *m1k, *m1q, *m2k, *m2q, *keys, *qrys, *qq, *wf;
    cudaGetSymbolAddress((void**)&feat, g_feat);
    cudaGetSymbolAddress((void**)&m1k, g_m1k);
    cudaGetSymbolAddress((void**)&m1q, g_m1q);
    cudaGetSymbolAddress((void**)&m2k, g_m2k);
    cudaGetSymbolAddress((void**)&m2q, g_m2q);
    cudaGetSymbolAddress((void**)&keys, g_keys);
    cudaGetSymbolAddress((void**)&qrys, g_qrys);
    cudaGetSymbolAddress((void**)&qq, g_qq);
    cudaGetSymbolAddress((void**)&wf, g_wf);
    __nv_bfloat16 *w1h, *w1l, *w2h, *w2l, *w3h, *w3l, *w4h, *w4l, *w5h, *w5l;
    cudaGetSymbolAddress((void**)&w1h, g_w1h); cudaGetSymbolAddress((void**)&w1l, g_w1l);
    cudaGetSymbolAddress((void**)&w2h, g_w2h); cudaGetSymbolAddress((void**)&w2l, g_w2l);
    cudaGetSymbolAddress((void**)&w3h, g_w3h); cudaGetSymbolAddress((void**)&w3l, g_w3l);
    cudaGetSymbolAddress((void**)&w4h, g_w4h); cudaGetSymbolAddress((void**)&w4l, g_w4l);
    cudaGetSymbolAddress((void**)&w5h, g_w5h); cudaGetSymbolAddress((void**)&w5l, g_w5l);

    constexpr int SMEM_S = 2 * 55296;   // 110592, 2 CTAs/SM

    cudaFuncSetAttribute(convMMA_kernel<256, 512, 16, 16, 1, 0, 64, 2, 2>,
                         cudaFuncAttributeMaxDynamicSharedMemorySize, SMEM_S);
    cudaFuncSetAttribute(convMMA_kernel<512, 256, 16, 16, 1, 0, 64, 2, 2>,
                         cudaFuncAttributeMaxDynamicSharedMemorySize, SMEM_S);
    cudaFuncSetAttribute(convMMA_kernel<256, 256, 16, 16, 2, 0, 64, 2, 2>,
                         cudaFuncAttributeMaxDynamicSharedMemorySize, SMEM_S);
    cudaFuncSetAttribute(convMMA_kernel<256, 256, 8, 8, 1, 0, 64, 2, 2>,
                         cudaFuncAttributeMaxDynamicSharedMemorySize, SMEM_S);
    cudaFuncSetAttribute(convMMA_kernel<256, 256, 8, 8, 2, 1, 64, 2, 2>,
                         cudaFuncAttributeMaxDynamicSharedMemorySize, SMEM_S);

    // ---- launch 0: all weight preps in one kernel ----
    {
        int t1 = 512 * 2304, t2 = 256 * 4608, t3 = 256 * 2304;
        WPrepDesc d0 = {cw[0], w1h, w1l, 256, t1, 0};
        WPrepDesc d1 = {cw[1], w2h, w2l, 512, t2, t1};
        WPrepDesc d2 = {cw[2], w3h, w3l, 256, t3, t1 + t2};
        WPrepDesc d3 = {cw[3], w4h, w4l, 256, t3, t1 + t2 + t3};
        WPrepDesc d4 = {cw[4], w5h, w5l, 256, t3, t1 + t2 + 2 * t3};
        int grand = t1 + t2 + 3 * t3;
        wprep_all_kernel<<<1184, 256>>>(d0, d1, d2, d3, d4, grand);
    }
    // ---- launch 1: bevs split ----
    actsplit_kernel<<<dim3(160, 8), 256>>>(bevs, a0h, a0l);

    // ---- launches 2..6: conv stack, all MTILE=64 @ 2 CTAs/SM ----
    convMMA_kernel<256, 512, 16, 16, 1, 0, 64, 2, 2><<<dim3(16, 160), 256, SMEM_S>>>(
        a0h, a0l, w1h, w1l, cs[0], ct[0], b1h, b1l, nullptr);
    convMMA_kernel<512, 256, 16, 16, 1, 0, 64, 2, 2><<<dim3(8, 160), 256, SMEM_S>>>(
        b1h, b1l, w2h, w2l, cs[1], ct[1], b2h, b2l, nullptr);
    convMMA_kernel<256, 256, 16, 16, 2, 0, 64, 2, 2><<<dim3(2, 160), 256, SMEM_S>>>(
        b2h, b2l, w3h, w3l, cs[2], ct[2], b3h, b3l, nullptr);
    convMMA_kernel<256, 256, 8, 8, 1, 0, 64, 2, 2><<<dim3(2, 160), 256, SMEM_S>>>(
        b3h, b3l, w4h, w4l, cs[3], ct[3], b4h, b4l, nullptr);
    convMMA_kernel<256, 256, 8, 8, 2, 1, 64, 2, 2><<<dim3(2, 40), 256, SMEM_S>>>(
        b4h, b4l, w5h, w5l, cs[4], ct[4], nullptr, nullptr, feat);

    // ---- fused k/q tail ----
    auto wt2 = [&](const float* X1, const float* W1, const float* B1, float* Y1, int N1,
                   const float* X2, const float* W2, const float* B2, float* Y2, int N2,
                   int M, int K, int relu) {
        int warps = (M / 4) * ((N1 + N2) / 8);
        warptile2_kernel<<<(warps + 7) / 8, 256>>>(X1, W1, B1, Y1, N1,
                                                   X2, W2, B2, Y2, N2, M, K, relu);
    };
    wt2(feat, kw1, kb1, m1k, 256, feat, qw1, qb1, m1q, 256, 160, 4096, 1);
    wt2(m1k, kw2, kb2, m2k, 128, m1q, qw2, qb2, m2q, 128, 160, 256, 1);
    wt2(m2k, kw3, kb3, keys, 1024, m2q, qw3, qb3, qrys, 32, 160, 128, 0);
    {
        int warps = (160 / 4) * (1024 / 8);
        warptile_kernel<<<(warps + 7) / 8, 256>>>(qrys, aw, ab, qq, 160, 1024, 32, 0);
    }

    attn_kernel<<<32, 256>>>(keys, qq, wf);
    fuse_kernel<<<(32 * 256 * 16 * 16 + 255) / 256, 256>>>(bevs, wf, out);
}

// round 16
// speedup vs baseline: 2.1398x; 1.4141x over previous
#include <cuda_runtime.h>
#include <cuda_fp16.h>
#include <cstdint>
#include <cstddef>

// ===========================================================================
// Who2com forward — 2-term fp16 mma.sync implicit-GEMM convs.
// R16: A = fp16 hi+lo (22 bits), B = single fp16 (11 bits);
//      d = ah*bh + al*bh  (2 MMAs per k-step vs 3 before).
// Stage = A_hi + A_lo + B_hi = 36.9KB -> 3 stages @ 2 CTAs/SM.
// ===========================================================================

__device__ __forceinline__ uint32_t smem_to_u32(const void* p) {
    uint32_t a;
    asm("{ .reg .u64 t; cvta.to.shared.u64 t, %1; cvt.u32.u64 %0, t; }"
        : "=r"(a) : "l"(p));
    return a;
}
__device__ __forceinline__ void ldsm_x4(uint32_t (&r)[4], uint32_t addr) {
    asm volatile("ldmatrix.sync.aligned.m8n8.x4.shared.b16 {%0,%1,%2,%3}, [%4];"
                 : "=r"(r[0]), "=r"(r[1]), "=r"(r[2]), "=r"(r[3]) : "r"(addr));
}
__device__ __forceinline__ void mma_f16(float (&d)[4], const uint32_t (&a)[4],
                                        uint32_t b0, uint32_t b1) {
    asm volatile(
        "mma.sync.aligned.m16n8k16.row.col.f32.f16.f16.f32 "
        "{%0,%1,%2,%3}, {%4,%5,%6,%7}, {%8,%9}, {%0,%1,%2,%3};"
        : "+f"(d[0]), "+f"(d[1]), "+f"(d[2]), "+f"(d[3])
        : "r"(a[0]), "r"(a[1]), "r"(a[2]), "r"(a[3]), "r"(b0), "r"(b1));
}
__device__ __forceinline__ uint32_t pack_h2(__half a, __half b) {
    __half2 t = __halves2half2(a, b);
    return *reinterpret_cast<uint32_t*>(&t);
}
__device__ __forceinline__ void cp16(uint32_t dst, const void* src, bool v) {
    asm volatile("cp.async.cg.shared.global [%0], [%1], 16, %2;"
                 :: "r"(dst), "l"(src), "r"(v ? 16u : 0u) : "memory");
}
#define CP_COMMIT() asm volatile("cp.async.commit_group;" ::: "memory")

// ---------------------------------------------------------------------------
// Scratch
// ---------------------------------------------------------------------------
__device__ __align__(16) __half g_a0h[(size_t)160 * 256 * 256];
__device__ __align__(16) __half g_a0l[(size_t)160 * 256 * 256];
__device__ __align__(16) __half g_b1h[(size_t)160 * 256 * 512];
__device__ __align__(16) __half g_b1l[(size_t)160 * 256 * 512];
__device__ __align__(16) __half g_b2h[(size_t)160 * 256 * 256];
__device__ __align__(16) __half g_b2l[(size_t)160 * 256 * 256];
__device__ __align__(16) __half g_b3h[(size_t)160 * 64 * 256];
__device__ __align__(16) __half g_b3l[(size_t)160 * 64 * 256];
__device__ __align__(16) __half g_b4h[(size_t)160 * 64 * 256];
__device__ __align__(16) __half g_b4l[(size_t)160 * 64 * 256];
__device__ float g_feat[(size_t)160 * 4096];
__device__ float g_m1k[160 * 256], g_m1q[160 * 256];
__device__ float g_m2k[160 * 128], g_m2q[160 * 128];
__device__ float g_keys[160 * 1024];
__device__ float g_qrys[160 * 32];
__device__ float g_qq[160 * 1024];
__device__ float g_wf[32 * 5];
__device__ __align__(16) __half g_w1h[512 * 2304];
__device__ __align__(16) __half g_w2h[256 * 4608];
__device__ __align__(16) __half g_w3h[256 * 2304];
__device__ __align__(16) __half g_w4h[256 * 2304];
__device__ __align__(16) __half g_w5h[256 * 2304];

// ---------------------------------------------------------------------------
// Merged weight prep: all 5 conv layers; fp16 hi only.
// src[co][ci][kh][kw] -> fp16 at [co][(kh*3+kw)*CIN + ci]
// ---------------------------------------------------------------------------
struct WPrepDesc {
    const float* src;
    __half* hi;
    int cin;
    int total;
    int base;
};

__global__ void wprep_all_kernel(WPrepDesc d0, WPrepDesc d1, WPrepDesc d2,
                                 WPrepDesc d3, WPrepDesc d4, int grand)
{
    WPrepDesc ds[5] = {d0, d1, d2, d3, d4};
    for (int g = blockIdx.x * blockDim.x + threadIdx.x; g < grand;
         g += gridDim.x * blockDim.x) {
        int li = 0;
#pragma unroll
        for (int t = 1; t < 5; t++)
            if (g >= ds[t].base) li = t;
        const WPrepDesc& d = ds[li];
        int idx = g - d.base;
        int cin9 = d.cin * 9;
        int co = idx / cin9;
        int rem = idx - co * cin9;
        int ci = rem / 9, tap = rem - ci * 9;
        d.hi[(size_t)co * cin9 + tap * d.cin + ci] = __float2half(d.src[idx]);
    }
}

// bevs NCHW fp32 -> NHWC fp16 hi/lo.
__global__ void actsplit_kernel(const float* __restrict__ in,
                                __half* __restrict__ oh,
                                __half* __restrict__ ol)
{
    __shared__ float s[32][257];
    int n = blockIdx.x, c0 = blockIdx.y * 32;
    int tid = threadIdx.x;
#pragma unroll
    for (int it = 0; it < 32; it++)
        s[it][tid] = in[((size_t)n * 256 + c0 + it) * 256 + tid];
    __syncthreads();
    int ci = tid & 31, p0 = tid >> 5;
#pragma unroll
    for (int pp = 0; pp < 32; pp++) {
        int pix = p0 + pp * 8;
        float v = s[ci][pix];
        __half h = __float2half(v);
        __half l = __float2half(v - __half2float(h));
        size_t o = ((size_t)n * 256 + pix) * 256 + c0 + ci;
        oh[o] = h; ol[o] = l;
    }
}

// ---------------------------------------------------------------------------
// Implicit-GEMM conv3x3 (pad=1) + affine + ReLU, 2-term fp16 mma.sync.
// K-chunks of 64 (144B pitch), circular 3-stage cp.async pipeline, one
// __syncthreads per chunk.
// ---------------------------------------------------------------------------
static constexpr int SPB = 144;

template <int CIN, int COUT, int HIN, int WIN, int STRIDE, int OUTMODE,
          int MTILE, int STAGES, int MINCTA>
__global__ void __launch_bounds__(256, MINCTA)
convMMA_kernel(const __half* __restrict__ aH, const __half* __restrict__ aL,
               const __half* __restrict__ wH,
               const float* __restrict__ scale, const float* __restrict__ shift,
               __half* __restrict__ oH, __half* __restrict__ oL,
               float* __restrict__ oF)
{
    constexpr int HO   = (HIN - 1) / STRIDE + 1;
    constexpr int WO   = (WIN - 1) / STRIDE + 1;
    constexpr int MPIX = HO * WO;
    constexpr int NIMG = (MPIX >= MTILE) ? 1 : (MTILE / MPIX);
    constexpr int NT   = COUT / 128;
    constexpr int KTOT = 9 * CIN;
    constexpr int CPT  = CIN / 64;
    constexpr int NCH  = 9 * CPT;
    constexpr int MW   = MTILE / 32;
    constexpr int NW   = 8 / MW;
    constexpr int NCPW = 128 / NW;
    constexpr int NT2  = NCPW / 16;
    constexpr int STB  = (2 * MTILE + 128) * SPB;   // A_hi + A_lo + B_hi
    constexpr int A_LO = MTILE * SPB;
    constexpr int B_HI = 2 * MTILE * SPB;
    constexpr int RT   = (2 * MTILE + 128) * 8;     // cp16 transfers per stage

    extern __shared__ char smem[];
    const uint32_t sb = smem_to_u32(smem);

    const int tid = threadIdx.x, wid = tid >> 5, lane = tid & 31;
    const int mt  = blockIdx.x / NT;
    const int co0 = (blockIdx.x % NT) * 128;
    const int n0  = blockIdx.y * NIMG;
    const int wm  = wid % MW;
    const int wn  = wid / MW;

    auto issue = [&](int c) {
        const uint32_t st = sb + (uint32_t)(c % STAGES) * STB;
        const int tap = c / CPT;
        const int ci0 = (c - tap * CPT) * 64;
        const int dy = tap / 3 - 1, dx = tap % 3 - 1;
#pragma unroll
        for (int i = tid; i < RT; i += 256) {
            const int row = i >> 3;
            const int seg = i & 7;
            if (row < 2 * MTILE) {
                const int half = (row >= MTILE) ? 1 : 0;
                const int r = row - half * MTILE;
                int g = mt * MTILE + r;
                int img = g / MPIX, pix = g % MPIX;
                int oh = pix / WO, ow = pix - oh * WO;
                int ih = oh * STRIDE + dy, iw = ow * STRIDE + dx;
                bool v = ((unsigned)ih < (unsigned)HIN) && ((unsigned)iw < (unsigned)WIN);
                int ihs = v ? ih : 0, iws = v ? iw : 0;
                size_t aoff = (((size_t)(n0 + img) * HIN + ihs) * WIN + iws) * CIN
                              + ci0 + seg * 8;
                uint32_t ad = st + (uint32_t)half * A_LO + (uint32_t)r * SPB + seg * 16;
                cp16(ad, (half ? aL : aH) + aoff, v);
            } else {
                int r2 = row - 2 * MTILE;
                size_t woff = (size_t)(co0 + r2) * KTOT + (size_t)c * 64 + seg * 8;
                uint32_t bd = st + B_HI + (uint32_t)r2 * SPB + seg * 16;
                cp16(bd, wH + woff, true);
            }
        }
        CP_COMMIT();
    };

    float acc[2][NT2 * 2][4];
#pragma unroll
    for (int a = 0; a < 2; a++)
#pragma unroll
        for (int b = 0; b < NT2 * 2; b++)
#pragma unroll
            for (int c = 0; c < 4; c++) acc[a][b][c] = 0.f;

#pragma unroll
    for (int p = 0; p < STAGES - 1; p++) issue(p);

    for (int c = 0; c < NCH; c++) {
        asm volatile("cp.async.wait_group %0;" :: "n"(STAGES - 2) : "memory");
        __syncthreads();
        if (c + STAGES - 1 < NCH) issue(c + STAGES - 1);
        else CP_COMMIT();

        const uint32_t st  = sb + (uint32_t)(c % STAGES) * STB;
        const uint32_t sAh = st, sAl = st + A_LO, sBh = st + B_HI;
#pragma unroll
        for (int ks = 0; ks < 4; ks++) {
            // ---- fragment loads for this ks ----
            const uint32_t acol = (uint32_t)ks * 32u + ((lane >> 4) << 4);
            uint32_t ah[2][4], al2[2][4];
#pragma unroll
            for (int m2 = 0; m2 < 2; m2++) {
                uint32_t arow = (uint32_t)(wm * 32 + m2 * 16 + (lane & 15));
                ldsm_x4(ah[m2],  sAh + arow * SPB + acol);
                ldsm_x4(al2[m2], sAl + arow * SPB + acol);
            }
            uint32_t bh[NT2][4];
            const uint32_t bcol = (uint32_t)ks * 32u + (((lane >> 3) & 1) << 4);
#pragma unroll
            for (int nt2 = 0; nt2 < NT2; nt2++) {
                uint32_t brow = (uint32_t)(wn * NCPW + nt2 * 16 +
                                           ((lane >> 4) << 3) + (lane & 7));
                ldsm_x4(bh[nt2], sBh + brow * SPB + bcol);
            }
            // ---- pass 1: ah * bh ----
#pragma unroll
            for (int nt2 = 0; nt2 < NT2; nt2++)
#pragma unroll
                for (int m2 = 0; m2 < 2; m2++) {
                    mma_f16(acc[m2][nt2 * 2],     ah[m2], bh[nt2][0], bh[nt2][1]);
                    mma_f16(acc[m2][nt2 * 2 + 1], ah[m2], bh[nt2][2], bh[nt2][3]);
                }
            // ---- pass 2: al * bh ----
#pragma unroll
            for (int nt2 = 0; nt2 < NT2; nt2++)
#pragma unroll
                for (int m2 = 0; m2 < 2; m2++) {
                    mma_f16(acc[m2][nt2 * 2],     al2[m2], bh[nt2][0], bh[nt2][1]);
                    mma_f16(acc[m2][nt2 * 2 + 1], al2[m2], bh[nt2][2], bh[nt2][3]);
                }
        }
    }

    if (OUTMODE == 0) {
#pragma unroll
        for (int m2 = 0; m2 < 2; m2++) {
            int mA = wm * 32 + m2 * 16 + (lane >> 2);
            int gA = mt * MTILE + mA;
            int gB = gA + 8;
            size_t rowA = ((size_t)(n0 + gA / MPIX) * MPIX + gA % MPIX) * COUT;
            size_t rowB = ((size_t)(n0 + gB / MPIX) * MPIX + gB % MPIX) * COUT;
#pragma unroll
            for (int j = 0; j < NT2 * 2; j++) {
                int co = co0 + wn * NCPW + j * 8 + (lane & 3) * 2;
                float s0 = __ldg(scale + co), s1 = __ldg(scale + co + 1);
                float t0 = __ldg(shift + co), t1 = __ldg(shift + co + 1);
                float v0 = fmaxf(fmaf(acc[m2][j][0], s0, t0), 0.f);
                float v1 = fmaxf(fmaf(acc[m2][j][1], s1, t1), 0.f);
                float v2 = fmaxf(fmaf(acc[m2][j][2], s0, t0), 0.f);
                float v3 = fmaxf(fmaf(acc[m2][j][3], s1, t1), 0.f);
                __half h0 = __float2half(v0), h1 = __float2half(v1);
                __half h2 = __float2half(v2), h3 = __float2half(v3);
                __half l0 = __float2half(v0 - __half2float(h0));
                __half l1 = __float2half(v1 - __half2float(h1));
                __half l2 = __float2half(v2 - __half2float(h2));
                __half l3 = __float2half(v3 - __half2float(h3));
                *reinterpret_cast<uint32_t*>(oH + rowA + co) = pack_h2(h0, h1);
                *reinterpret_cast<uint32_t*>(oL + rowA + co) = pack_h2(l0, l1);
                *reinterpret_cast<uint32_t*>(oH + rowB + co) = pack_h2(h2, h3);
                *reinterpret_cast<uint32_t*>(oL + rowB + co) = pack_h2(l2, l3);
            }
        }
    } else {
        constexpr int OPITCH = MTILE + 4;
        float* sOut = reinterpret_cast<float*>(smem);
        __syncthreads();
#pragma unroll
        for (int m2 = 0; m2 < 2; m2++) {
#pragma unroll
            for (int j = 0; j < NT2 * 2; j++) {
                int m = wm * 32 + m2 * 16 + (lane >> 2);
                int nn = wn * NCPW + j * 8 + (lane & 3) * 2;
                sOut[(size_t)nn * OPITCH + m]           = acc[m2][j][0];
                sOut[(size_t)(nn + 1) * OPITCH + m]     = acc[m2][j][1];
                sOut[(size_t)nn * OPITCH + m + 8]       = acc[m2][j][2];
                sOut[(size_t)(nn + 1) * OPITCH + m + 8] = acc[m2][j][3];
            }
        }
        __syncthreads();
        int row = tid >> 1, half = tid & 1;
        int co = co0 + row;
        float s = __ldg(scale + co), t = __ldg(shift + co);
#pragma unroll
        for (int q = 0; q < MTILE / 8; q++) {
            int m = half * (MTILE / 2) + q * 4;
            float4 v = *reinterpret_cast<float4*>(&sOut[(size_t)row * OPITCH + m]);
            v.x = fmaxf(fmaf(v.x, s, t), 0.f);
            v.y = fmaxf(fmaf(v.y, s, t), 0.f);
            v.z = fmaxf(fmaf(v.z, s, t), 0.f);
            v.w = fmaxf(fmaf(v.w, s, t), 0.f);
            int g = mt * MTILE + m;
            int img = g / MPIX, pix = g % MPIX;
            *reinterpret_cast<float4*>(
                &oF[((size_t)(n0 + img) * COUT + co) * MPIX + pix]) = v;
        }
    }
}

// ---------------------------------------------------------------------------
// Warp-tile GEMV over TWO independent (X,W,b,Y,N) sets in one launch.
// ---------------------------------------------------------------------------
__global__ void warptile2_kernel(const float* __restrict__ X1, const float* __restrict__ W1,
                                 const float* __restrict__ B1, float* __restrict__ Y1, int N1,
                                 const float* __restrict__ X2, const float* __restrict__ W2,
                                 const float* __restrict__ B2, float* __restrict__ Y2, int N2,
                                 int M, int K, int doRelu)
{
    int gw   = (blockIdx.x * blockDim.x + threadIdx.x) >> 5;
    int lane = threadIdx.x & 31;
    int nWtot = (N1 + N2) >> 3;
    int mtile = gw / nWtot, ntile = gw - mtile * nWtot;
    if (mtile * 4 >= M) return;
    const float *X, *W, *Bb;
    float* Y;
    int N, nt;
    if (ntile < (N1 >> 3)) { X = X1; W = W1; Bb = B1; Y = Y1; N = N1; nt = ntile; }
    else { X = X2; W = W2; Bb = B2; Y = Y2; N = N2; nt = ntile - (N1 >> 3); }
    const float* x0 = X + (size_t)(mtile * 4) * K;
    const float* w0 = W + (size_t)(nt * 8) * K;
    float acc[4][8];
#pragma unroll
    for (int i = 0; i < 4; i++)
#pragma unroll
        for (int j = 0; j < 8; j++) acc[i][j] = 0.f;
    for (int k = lane; k < K; k += 32) {
        float xv[4], wv[8];
#pragma unroll
        for (int i = 0; i < 4; i++) xv[i] = x0[(size_t)i * K + k];
#pragma unroll
        for (int j = 0; j < 8; j++) wv[j] = w0[(size_t)j * K + k];
#pragma unroll
        for (int i = 0; i < 4; i++)
#pragma unroll
            for (int j = 0; j < 8; j++) acc[i][j] = fmaf(xv[i], wv[j], acc[i][j]);
    }
#pragma unroll
    for (int o = 16; o; o >>= 1)
#pragma unroll
        for (int i = 0; i < 4; i++)
#pragma unroll
            for (int j = 0; j < 8; j++)
                acc[i][j] += __shfl_xor_sync(0xffffffffu, acc[i][j], o);
    int i = lane >> 3, j = lane & 7;
    float v = acc[i][j] + Bb[nt * 8 + j];
    if (doRelu) v = fmaxf(v, 0.f);
    Y[(size_t)(mtile * 4 + i) * N + nt * 8 + j] = v;
}

__global__ void warptile_kernel(const float* __restrict__ X, const float* __restrict__ W,
                                const float* __restrict__ bias, float* __restrict__ Y,
                                int M, int N, int K, int doRelu)
{
    int gw   = (blockIdx.x * blockDim.x + threadIdx.x) >> 5;
    int lane = threadIdx.x & 31;
    int nW = N >> 3;
    int mtile = gw / nW, ntile = gw - mtile * nW;
    if (mtile * 4 >= M) return;
    const float* x0 = X + (size_t)(mtile * 4) * K;
    const float* w0 = W + (size_t)(ntile * 8) * K;
    float acc[4][8];
#pragma unroll
    for (int i = 0; i < 4; i++)
#pragma unroll
        for (int j = 0; j < 8; j++) acc[i][j] = 0.f;
    for (int k = lane; k < K; k += 32) {
        float xv[4], wv[8];
#pragma unroll
        for (int i = 0; i < 4; i++) xv[i] = x0[(size_t)i * K + k];
#pragma unroll
        for (int j = 0; j < 8; j++) wv[j] = w0[(size_t)j * K + k];
#pragma unroll
        for (int i = 0; i < 4; i++)
#pragma unroll
            for (int j = 0; j < 8; j++) acc[i][j] = fmaf(xv[i], wv[j], acc[i][j]);
    }
#pragma unroll
    for (int o = 16; o; o >>= 1)
#pragma unroll
        for (int i = 0; i < 4; i++)
#pragma unroll
            for (int j = 0; j < 8; j++)
                acc[i][j] += __shfl_xor_sync(0xffffffffu, acc[i][j], o);
    int i = lane >> 3, j = lane & 7;
    float v = acc[i][j] + bias[ntile * 8 + j];
    if (doRelu) v = fmaxf(v, 0.f);
    Y[(size_t)(mtile * 4 + i) * N + ntile * 8 + j] = v;
}

// ---------------------------------------------------------------------------
// Attention + softmax -> fuse weights; final fuse.
// ---------------------------------------------------------------------------
__global__ void attn_kernel(const float* __restrict__ keys, const float* __restrict__ qq,
                            float* __restrict__ wf)
{
    int b = blockIdx.x;
    __shared__ float sA[5][5];
    int warp = threadIdx.x >> 5, lane = threadIdx.x & 31;
    for (int e = warp; e < 25; e += 8) {
        int i = e / 5, j = e - i * 5;
        const float4* kr = (const float4*)(keys + (size_t)(i * 32 + b) * 1024);
        const float4* qr = (const float4*)(qq + (size_t)(j * 32 + b) * 1024);
        float acc = 0.f;
        for (int k = lane; k < 256; k += 32) {
            float4 a = kr[k], c = qr[k];
            acc += a.x * c.x + a.y * c.y + a.z * c.z + a.w * c.w;
        }
#pragma unroll
        for (int o = 16; o; o >>= 1) acc += __shfl_xor_sync(0xffffffffu, acc, o);
        if (lane == 0) sA[i][j] = acc;
    }
    __syncthreads();
    if (threadIdx.x == 0) {
        float w[5] = {0.f, 0.f, 0.f, 0.f, 0.f};
        for (int j = 0; j < 5; j++) {
            float dd[4], mx = -1e30f;
            for (int r = 0; r < 4; r++) {
                dd[r] = (j > r) ? sA[r][j] : sA[r + 1][j];
                mx = fmaxf(mx, dd[r]);
            }
            float s = 0.f;
            for (int r = 0; r < 4; r++) { dd[r] = expf(dd[r] - mx); s += dd[r]; }
            float inv = 1.f / s;
            for (int r = 0; r < 4; r++) {
                int i = (j > r) ? r : r + 1;
                w[i] += dd[r] * inv;
            }
        }
        for (int i = 0; i < 5; i++) wf[b * 5 + i] = w[i] * 0.2f;
    }
}

__global__ void fuse_kernel(const float* __restrict__ bevs, const float* __restrict__ wf,
                            float* __restrict__ out)
{
    const int CHW = 256 * 16 * 16;
    int idx = blockIdx.x * blockDim.x + threadIdx.x;
    if (idx >= 32 * CHW) return;
    int b   = idx / CHW;
    int chw = idx - b * CHW;
    const float* base = bevs + ((size_t)b * 5) * CHW + chw;
    float acc = 0.f;
#pragma unroll
    for (int k = 0; k < 5; k++) acc += wf[b * 5 + k] * base[(size_t)k * CHW];
    out[idx] = acc;
}

// ---------------------------------------------------------------------------
extern "C" void kernel_launch(void* const* d_in, const int* in_sizes, int n_in,
                              void* d_out, int out_size)
{
    (void)in_sizes; (void)n_in; (void)out_size;
    const float* bevs = (const float*)d_in[0];
    const float *cw[5], *cs[5], *ct[5];
    for (int i = 0; i < 5; i++) {
        cw[i] = (const float*)d_in[1 + 3 * i];
        cs[i] = (const float*)d_in[2 + 3 * i];
        ct[i] = (const float*)d_in[3 + 3 * i];
    }
    const float* kw1 = (const float*)d_in[16]; const float* kb1 = (const float*)d_in[17];
    const float* kw2 = (const float*)d_in[18]; const float* kb2 = (const float*)d_in[19];
    const float* kw3 = (const float*)d_in[20]; const float* kb3 = (const float*)d_in[21];
    const float* qw1 = (const float*)d_in[22]; const float* qb1 = (const float*)d_in[23];
    const float* qw2 = (const float*)d_in[24]; const float* qb2 = (const float*)d_in[25];
    const float* qw3 = (const float*)d_in[26]; const float* qb3 = (const float*)d_in[27];
    const float* aw  = (const float*)d_in[28]; const float* ab  = (const float*)d_in[29];
    float* out = (float*)d_out;

    __half *a0h, *a0l, *b1h, *b1l, *b2h, *b2l, *b3h, *b3l, *b4h, *b4l;
    cudaGetSymbolAddress((void**)&a0h, g_a0h); cudaGetSymbolAddress((void**)&a0l, g_a0l);
    cudaGetSymbolAddress((void**)&b1h, g_b1h); cudaGetSymbolAddress((void**)&b1l, g_b1l);
    cudaGetSymbolAddress((void**)&b2h, g_b2h); cudaGetSymbolAddress((void**)&b2l, g_b2l);
    cudaGetSymbolAddress((void**)&b3h, g_b3h); cudaGetSymbolAddress((void**)&b3l, g_b3l);
    cudaGetSymbolAddress((void**)&b4h, g_b4h); cudaGetSymbolAddress((void**)&b4l, g_b4l);
    float *feat, *m1k, *m1q, *m2k, *m2q, *keys, *qrys, *qq, *wf;
    cudaGetSymbolAddress((void**)&feat, g_feat);
    cudaGetSymbolAddress((void**)&m1k, g_m1k);
    cudaGetSymbolAddress((void**)&m1q, g_m1q);
    cudaGetSymbolAddress((void**)&m2k, g_m2k);
    cudaGetSymbolAddress((void**)&m2q, g_m2q);
    cudaGetSymbolAddress((void**)&keys, g_keys);
    cudaGetSymbolAddress((void**)&qrys, g_qrys);
    cudaGetSymbolAddress((void**)&qq, g_qq);
    cudaGetSymbolAddress((void**)&wf, g_wf);
    __half *w1h, *w2h, *w3h, *w4h, *w5h;
    cudaGetSymbolAddress((void**)&w1h, g_w1h);
    cudaGetSymbolAddress((void**)&w2h, g_w2h);
    cudaGetSymbolAddress((void**)&w3h, g_w3h);
    cudaGetSymbolAddress((void**)&w4h, g_w4h);
    cudaGetSymbolAddress((void**)&w5h, g_w5h);

    // stage = (2*64+128)*144 = 36864B; 3 stages = 110592 -> 2 CTAs/SM
    constexpr int SMEM_S = 3 * 36864;

    cudaFuncSetAttribute(convMMA_kernel<256, 512, 16, 16, 1, 0, 64, 3, 2>,
                         cudaFuncAttributeMaxDynamicSharedMemorySize, SMEM_S);
    cudaFuncSetAttribute(convMMA_kernel<512, 256, 16, 16, 1, 0, 64, 3, 2>,
                         cudaFuncAttributeMaxDynamicSharedMemorySize, SMEM_S);
    cudaFuncSetAttribute(convMMA_kernel<256, 256, 16, 16, 2, 0, 64, 3, 2>,
                         cudaFuncAttributeMaxDynamicSharedMemorySize, SMEM_S);
    cudaFuncSetAttribute(convMMA_kernel<256, 256, 8, 8, 1, 0, 64, 3, 2>,
                         cudaFuncAttributeMaxDynamicSharedMemorySize, SMEM_S);
    cudaFuncSetAttribute(convMMA_kernel<256, 256, 8, 8, 2, 1, 64, 3, 2>,
                         cudaFuncAttributeMaxDynamicSharedMemorySize, SMEM_S);

    // ---- launch 0: all weight preps in one kernel ----
    {
        int t1 = 512 * 2304, t2 = 256 * 4608, t3 = 256 * 2304;
        WPrepDesc d0 = {cw[0], w1h, 256, t1, 0};
        WPrepDesc d1 = {cw[1], w2h, 512, t2, t1};
        WPrepDesc d2 = {cw[2], w3h, 256, t3, t1 + t2};
        WPrepDesc d3 = {cw[3], w4h, 256, t3, t1 + t2 + t3};
        WPrepDesc d4 = {cw[4], w5h, 256, t3, t1 + t2 + 2 * t3};
        int grand = t1 + t2 + 3 * t3;
        wprep_all_kernel<<<1184, 256>>>(d0, d1, d2, d3, d4, grand);
    }
    // ---- launch 1: bevs split ----
    actsplit_kernel<<<dim3(160, 8), 256>>>(bevs, a0h, a0l);

    // ---- launches 2..6: conv stack ----
    convMMA_kernel<256, 512, 16, 16, 1, 0, 64, 3, 2><<<dim3(16, 160), 256, SMEM_S>>>(
        a0h, a0l, w1h, cs[0], ct[0], b1h, b1l, nullptr);
    convMMA_kernel<512, 256, 16, 16, 1, 0, 64, 3, 2><<<dim3(8, 160), 256, SMEM_S>>>(
        b1h, b1l, w2h, cs[1], ct[1], b2h, b2l, nullptr);
    convMMA_kernel<256, 256, 16, 16, 2, 0, 64, 3, 2><<<dim3(2, 160), 256, SMEM_S>>>(
        b2h, b2l, w3h, cs[2], ct[2], b3h, b3l, nullptr);
    convMMA_kernel<256, 256, 8, 8, 1, 0, 64, 3, 2><<<dim3(2, 160), 256, SMEM_S>>>(
        b3h, b3l, w4h, cs[3], ct[3], b4h, b4l, nullptr);
    convMMA_kernel<256, 256, 8, 8, 2, 1, 64, 3, 2><<<dim3(2, 40), 256, SMEM_S>>>(
        b4h, b4l, w5h, cs[4], ct[4], nullptr, nullptr, feat);

    // ---- fused k/q tail ----
    auto wt2 = [&](const float* X1, const float* W1, const float* B1, float* Y1, int N1,
                   const float* X2, const float* W2, const float* B2, float* Y2, int N2,
                   int M, int K, int relu) {
        int warps = (M / 4) * ((N1 + N2) / 8);
        warptile2_kernel<<<(warps + 7) / 8, 256>>>(X1, W1, B1, Y1, N1,
                                                   X2, W2, B2, Y2, N2, M, K, relu);
    };
    wt2(feat, kw1, kb1, m1k, 256, feat, qw1, qb1, m1q, 256, 160, 4096, 1);
    wt2(m1k, kw2, kb2, m2k, 128, m1q, qw2, qb2, m2q, 128, 160, 256, 1);
    wt2(m2k, kw3, kb3, keys, 1024, m2q, qw3, qb3, qrys, 32, 160, 128, 0);
    {
        int warps = (160 / 4) * (1024 / 8);
        warptile_kernel<<<(warps + 7) / 8, 256>>>(qrys, aw, ab, qq, 160, 1024, 32, 0);
    }

    attn_kernel<<<32, 256>>>(keys, qq, wf);
    fuse_kernel<<<(32 * 256 * 16 * 16 + 255) / 256, 256>>>(bevs, wf, out);
}

// round 17
// speedup vs baseline: 3.3538x; 1.5674x over previous
#include <cuda_runtime.h>
#include <cuda_fp16.h>
#include <cstdint>
#include <cstddef>

// ===========================================================================
// Who2com forward — single-fp16 mma.sync implicit-GEMM convs.
// R17: A and B both single fp16 -> 1 MMA per k-step (was 2 in R16, 3 in R12).
// Stage = A + B = 27.6KB -> 4 stages @ 2 CTAs/SM. Evidence basis: R16 showed
// fp16 rounding of weights moved final rel_err by ~1e-10.
// ===========================================================================

__device__ __forceinline__ uint32_t smem_to_u32(const void* p) {
    uint32_t a;
    asm("{ .reg .u64 t; cvta.to.shared.u64 t, %1; cvt.u32.u64 %0, t; }"
        : "=r"(a) : "l"(p));
    return a;
}
__device__ __forceinline__ void ldsm_x4(uint32_t (&r)[4], uint32_t addr) {
    asm volatile("ldmatrix.sync.aligned.m8n8.x4.shared.b16 {%0,%1,%2,%3}, [%4];"
                 : "=r"(r[0]), "=r"(r[1]), "=r"(r[2]), "=r"(r[3]) : "r"(addr));
}
__device__ __forceinline__ void mma_f16(float (&d)[4], const uint32_t (&a)[4],
                                        uint32_t b0, uint32_t b1) {
    asm volatile(
        "mma.sync.aligned.m16n8k16.row.col.f32.f16.f16.f32 "
        "{%0,%1,%2,%3}, {%4,%5,%6,%7}, {%8,%9}, {%0,%1,%2,%3};"
        : "+f"(d[0]), "+f"(d[1]), "+f"(d[2]), "+f"(d[3])
        : "r"(a[0]), "r"(a[1]), "r"(a[2]), "r"(a[3]), "r"(b0), "r"(b1));
}
__device__ __forceinline__ uint32_t pack_h2(__half a, __half b) {
    __half2 t = __halves2half2(a, b);
    return *reinterpret_cast<uint32_t*>(&t);
}
__device__ __forceinline__ void cp16(uint32_t dst, const void* src, bool v) {
    asm volatile("cp.async.cg.shared.global [%0], [%1], 16, %2;"
                 :: "r"(dst), "l"(src), "r"(v ? 16u : 0u) : "memory");
}
#define CP_COMMIT() asm volatile("cp.async.commit_group;" ::: "memory")

// ---------------------------------------------------------------------------
// Scratch
// ---------------------------------------------------------------------------
__device__ __align__(16) __half g_a0h[(size_t)160 * 256 * 256];
__device__ __align__(16) __half g_b1h[(size_t)160 * 256 * 512];
__device__ __align__(16) __half g_b2h[(size_t)160 * 256 * 256];
__device__ __align__(16) __half g_b3h[(size_t)160 * 64 * 256];
__device__ __align__(16) __half g_b4h[(size_t)160 * 64 * 256];
__device__ float g_feat[(size_t)160 * 4096];
__device__ float g_m1k[160 * 256], g_m1q[160 * 256];
__device__ float g_m2k[160 * 128], g_m2q[160 * 128];
__device__ float g_keys[160 * 1024];
__device__ float g_qrys[160 * 32];
__device__ float g_qq[160 * 1024];
__device__ float g_wf[32 * 5];
__device__ __align__(16) __half g_w1h[512 * 2304];
__device__ __align__(16) __half g_w2h[256 * 4608];
__device__ __align__(16) __half g_w3h[256 * 2304];
__device__ __align__(16) __half g_w4h[256 * 2304];
__device__ __align__(16) __half g_w5h[256 * 2304];

// ---------------------------------------------------------------------------
// Merged weight prep: all 5 conv layers; fp16.
// ---------------------------------------------------------------------------
struct WPrepDesc {
    const float* src;
    __half* hi;
    int cin;
    int total;
    int base;
};

__global__ void wprep_all_kernel(WPrepDesc d0, WPrepDesc d1, WPrepDesc d2,
                                 WPrepDesc d3, WPrepDesc d4, int grand)
{
    WPrepDesc ds[5] = {d0, d1, d2, d3, d4};
    for (int g = blockIdx.x * blockDim.x + threadIdx.x; g < grand;
         g += gridDim.x * blockDim.x) {
        int li = 0;
#pragma unroll
        for (int t = 1; t < 5; t++)
            if (g >= ds[t].base) li = t;
        const WPrepDesc& d = ds[li];
        int idx = g - d.base;
        int cin9 = d.cin * 9;
        int co = idx / cin9;
        int rem = idx - co * cin9;
        int ci = rem / 9, tap = rem - ci * 9;
        d.hi[(size_t)co * cin9 + tap * d.cin + ci] = __float2half(d.src[idx]);
    }
}

// bevs NCHW fp32 -> NHWC fp16.
__global__ void actsplit_kernel(const float* __restrict__ in,
                                __half* __restrict__ oh)
{
    __shared__ float s[32][257];
    int n = blockIdx.x, c0 = blockIdx.y * 32;
    int tid = threadIdx.x;
#pragma unroll
    for (int it = 0; it < 32; it++)
        s[it][tid] = in[((size_t)n * 256 + c0 + it) * 256 + tid];
    __syncthreads();
    int ci = tid & 31, p0 = tid >> 5;
#pragma unroll
    for (int pp = 0; pp < 32; pp++) {
        int pix = p0 + pp * 8;
        oh[((size_t)n * 256 + pix) * 256 + c0 + ci] = __float2half(s[ci][pix]);
    }
}

// ---------------------------------------------------------------------------
// Implicit-GEMM conv3x3 (pad=1) + affine + ReLU, single-fp16 mma.sync.
// K-chunks of 64 (144B pitch), circular 4-stage cp.async pipeline, one
// __syncthreads per chunk.
// ---------------------------------------------------------------------------
static constexpr int SPB = 144;

template <int CIN, int COUT, int HIN, int WIN, int STRIDE, int OUTMODE,
          int MTILE, int STAGES, int MINCTA>
__global__ void __launch_bounds__(256, MINCTA)
convMMA_kernel(const __half* __restrict__ aH, const __half* __restrict__ wH,
               const float* __restrict__ scale, const float* __restrict__ shift,
               __half* __restrict__ oH, float* __restrict__ oF)
{
    constexpr int HO   = (HIN - 1) / STRIDE + 1;
    constexpr int WO   = (WIN - 1) / STRIDE + 1;
    constexpr int MPIX = HO * WO;
    constexpr int NIMG = (MPIX >= MTILE) ? 1 : (MTILE / MPIX);
    constexpr int NT   = COUT / 128;
    constexpr int KTOT = 9 * CIN;
    constexpr int CPT  = CIN / 64;
    constexpr int NCH  = 9 * CPT;
    constexpr int MW   = MTILE / 32;
    constexpr int NW   = 8 / MW;
    constexpr int NCPW = 128 / NW;
    constexpr int NT2  = NCPW / 16;
    constexpr int STB  = (MTILE + 128) * SPB;      // A + B
    constexpr int B_HI = MTILE * SPB;
    constexpr int RT   = (MTILE + 128) * 8;        // cp16 transfers per stage

    extern __shared__ char smem[];
    const uint32_t sb = smem_to_u32(smem);

    const int tid = threadIdx.x, wid = tid >> 5, lane = tid & 31;
    const int mt  = blockIdx.x / NT;
    const int co0 = (blockIdx.x % NT) * 128;
    const int n0  = blockIdx.y * NIMG;
    const int wm  = wid % MW;
    const int wn  = wid / MW;

    auto issue = [&](int c) {
        const uint32_t st = sb + (uint32_t)(c % STAGES) * STB;
        const int tap = c / CPT;
        const int ci0 = (c - tap * CPT) * 64;
        const int dy = tap / 3 - 1, dx = tap % 3 - 1;
#pragma unroll
        for (int i = tid; i < RT; i += 256) {
            const int row = i >> 3;
            const int seg = i & 7;
            if (row < MTILE) {
                int g = mt * MTILE + row;
                int img = g / MPIX, pix = g % MPIX;
                int oh = pix / WO, ow = pix - oh * WO;
                int ih = oh * STRIDE + dy, iw = ow * STRIDE + dx;
                bool v = ((unsigned)ih < (unsigned)HIN) && ((unsigned)iw < (unsigned)WIN);
                int ihs = v ? ih : 0, iws = v ? iw : 0;
                size_t aoff = (((size_t)(n0 + img) * HIN + ihs) * WIN + iws) * CIN
                              + ci0 + seg * 8;
                uint32_t ad = st + (uint32_t)row * SPB + seg * 16;
                cp16(ad, aH + aoff, v);
            } else {
                int r2 = row - MTILE;
                size_t woff = (size_t)(co0 + r2) * KTOT + (size_t)c * 64 + seg * 8;
                uint32_t bd = st + B_HI + (uint32_t)r2 * SPB + seg * 16;
                cp16(bd, wH + woff, true);
            }
        }
        CP_COMMIT();
    };

    float acc[2][NT2 * 2][4];
#pragma unroll
    for (int a = 0; a < 2; a++)
#pragma unroll
        for (int b = 0; b < NT2 * 2; b++)
#pragma unroll
            for (int c = 0; c < 4; c++) acc[a][b][c] = 0.f;

#pragma unroll
    for (int p = 0; p < STAGES - 1; p++) issue(p);

    for (int c = 0; c < NCH; c++) {
        asm volatile("cp.async.wait_group %0;" :: "n"(STAGES - 2) : "memory");
        __syncthreads();
        if (c + STAGES - 1 < NCH) issue(c + STAGES - 1);
        else CP_COMMIT();

        const uint32_t st  = sb + (uint32_t)(c % STAGES) * STB;
        const uint32_t sAh = st, sBh = st + B_HI;
#pragma unroll
        for (int ks = 0; ks < 4; ks++) {
            const uint32_t acol = (uint32_t)ks * 32u + ((lane >> 4) << 4);
            uint32_t ah[2][4];
#pragma unroll
            for (int m2 = 0; m2 < 2; m2++) {
                uint32_t arow = (uint32_t)(wm * 32 + m2 * 16 + (lane & 15));
                ldsm_x4(ah[m2], sAh + arow * SPB + acol);
            }
            uint32_t bh[NT2][4];
            const uint32_t bcol = (uint32_t)ks * 32u + (((lane >> 3) & 1) << 4);
#pragma unroll
            for (int nt2 = 0; nt2 < NT2; nt2++) {
                uint32_t brow = (uint32_t)(wn * NCPW + nt2 * 16 +
                                           ((lane >> 4) << 3) + (lane & 7));
                ldsm_x4(bh[nt2], sBh + brow * SPB + bcol);
            }
#pragma unroll
            for (int nt2 = 0; nt2 < NT2; nt2++)
#pragma unroll
                for (int m2 = 0; m2 < 2; m2++) {
                    mma_f16(acc[m2][nt2 * 2],     ah[m2], bh[nt2][0], bh[nt2][1]);
                    mma_f16(acc[m2][nt2 * 2 + 1], ah[m2], bh[nt2][2], bh[nt2][3]);
                }
        }
    }

    if (OUTMODE == 0) {
#pragma unroll
        for (int m2 = 0; m2 < 2; m2++) {
            int mA = wm * 32 + m2 * 16 + (lane >> 2);
            int gA = mt * MTILE + mA;
            int gB = gA + 8;
            size_t rowA = ((size_t)(n0 + gA / MPIX) * MPIX + gA % MPIX) * COUT;
            size_t rowB = ((size_t)(n0 + gB / MPIX) * MPIX + gB % MPIX) * COUT;
#pragma unroll
            for (int j = 0; j < NT2 * 2; j++) {
                int co = co0 + wn * NCPW + j * 8 + (lane & 3) * 2;
                float s0 = __ldg(scale + co), s1 = __ldg(scale + co + 1);
                float t0 = __ldg(shift + co), t1 = __ldg(shift + co + 1);
                float v0 = fmaxf(fmaf(acc[m2][j][0], s0, t0), 0.f);
                float v1 = fmaxf(fmaf(acc[m2][j][1], s1, t1), 0.f);
                float v2 = fmaxf(fmaf(acc[m2][j][2], s0, t0), 0.f);
                float v3 = fmaxf(fmaf(acc[m2][j][3], s1, t1), 0.f);
                *reinterpret_cast<uint32_t*>(oH + rowA + co) =
                    pack_h2(__float2half(v0), __float2half(v1));
                *reinterpret_cast<uint32_t*>(oH + rowB + co) =
                    pack_h2(__float2half(v2), __float2half(v3));
            }
        }
    } else {
        constexpr int OPITCH = MTILE + 4;
        float* sOut = reinterpret_cast<float*>(smem);
        __syncthreads();
#pragma unroll
        for (int m2 = 0; m2 < 2; m2++) {
#pragma unroll
            for (int j = 0; j < NT2 * 2; j++) {
                int m = wm * 32 + m2 * 16 + (lane >> 2);
                int nn = wn * NCPW + j * 8 + (lane & 3) * 2;
                sOut[(size_t)nn * OPITCH + m]           = acc[m2][j][0];
                sOut[(size_t)(nn + 1) * OPITCH + m]     = acc[m2][j][1];
                sOut[(size_t)nn * OPITCH + m + 8]       = acc[m2][j][2];
                sOut[(size_t)(nn + 1) * OPITCH + m + 8] = acc[m2][j][3];
            }
        }
        __syncthreads();
        int row = tid >> 1, half = tid & 1;
        int co = co0 + row;
        float s = __ldg(scale + co), t = __ldg(shift + co);
#pragma unroll
        for (int q = 0; q < MTILE / 8; q++) {
            int m = half * (MTILE / 2) + q * 4;
            float4 v = *reinterpret_cast<float4*>(&sOut[(size_t)row * OPITCH + m]);
            v.x = fmaxf(fmaf(v.x, s, t), 0.f);
            v.y = fmaxf(fmaf(v.y, s, t), 0.f);
            v.z = fmaxf(fmaf(v.z, s, t), 0.f);
            v.w = fmaxf(fmaf(v.w, s, t), 0.f);
            int g = mt * MTILE + m;
            int img = g / MPIX, pix = g % MPIX;
            *reinterpret_cast<float4*>(
                &oF[((size_t)(n0 + img) * COUT + co) * MPIX + pix]) = v;
        }
    }
}

// ---------------------------------------------------------------------------
// Warp-tile GEMV over TWO independent (X,W,b,Y,N) sets in one launch.
// ---------------------------------------------------------------------------
__global__ void warptile2_kernel(const float* __restrict__ X1, const float* __restrict__ W1,
                                 const float* __restrict__ B1, float* __restrict__ Y1, int N1,
                                 const float* __restrict__ X2, const float* __restrict__ W2,
                                 const float* __restrict__ B2, float* __restrict__ Y2, int N2,
                                 int M, int K, int doRelu)
{
    int gw   = (blockIdx.x * blockDim.x + threadIdx.x) >> 5;
    int lane = threadIdx.x & 31;
    int nWtot = (N1 + N2) >> 3;
    int mtile = gw / nWtot, ntile = gw - mtile * nWtot;
    if (mtile * 4 >= M) return;
    const float *X, *W, *Bb;
    float* Y;
    int N, nt;
    if (ntile < (N1 >> 3)) { X = X1; W = W1; Bb = B1; Y = Y1; N = N1; nt = ntile; }
    else { X = X2; W = W2; Bb = B2; Y = Y2; N = N2; nt = ntile - (N1 >> 3); }
    const float* x0 = X + (size_t)(mtile * 4) * K;
    const float* w0 = W + (size_t)(nt * 8) * K;
    float acc[4][8];
#pragma unroll
    for (int i = 0; i < 4; i++)
#pragma unroll
        for (int j = 0; j < 8; j++) acc[i][j] = 0.f;
    for (int k = lane; k < K; k += 32) {
        float xv[4], wv[8];
#pragma unroll
        for (int i = 0; i < 4; i++) xv[i] = x0[(size_t)i * K + k];
#pragma unroll
        for (int j = 0; j < 8; j++) wv[j] = w0[(size_t)j * K + k];
#pragma unroll
        for (int i = 0; i < 4; i++)
#pragma unroll
            for (int j = 0; j < 8; j++) acc[i][j] = fmaf(xv[i], wv[j], acc[i][j]);
    }
#pragma unroll
    for (int o = 16; o; o >>= 1)
#pragma unroll
        for (int i = 0; i < 4; i++)
#pragma unroll
            for (int j = 0; j < 8; j++)
                acc[i][j] += __shfl_xor_sync(0xffffffffu, acc[i][j], o);
    int i = lane >> 3, j = lane & 7;
    float v = acc[i][j] + Bb[nt * 8 + j];
    if (doRelu) v = fmaxf(v, 0.f);
    Y[(size_t)(mtile * 4 + i) * N + nt * 8 + j] = v;
}

__global__ void warptile_kernel(const float* __restrict__ X, const float* __restrict__ W,
                                const float* __restrict__ bias, float* __restrict__ Y,
                                int M, int N, int K, int doRelu)
{
    int gw   = (blockIdx.x * blockDim.x + threadIdx.x) >> 5;
    int lane = threadIdx.x & 31;
    int nW = N >> 3;
    int mtile = gw / nW, ntile = gw - mtile * nW;
    if (mtile * 4 >= M) return;
    const float* x0 = X + (size_t)(mtile * 4) * K;
    const float* w0 = W + (size_t)(ntile * 8) * K;
    float acc[4][8];
#pragma unroll
    for (int i = 0; i < 4; i++)
#pragma unroll
        for (int j = 0; j < 8; j++) acc[i][j] = 0.f;
    for (int k = lane; k < K; k += 32) {
        float xv[4], wv[8];
#pragma unroll
        for (int i = 0; i < 4; i++) xv[i] = x0[(size_t)i * K + k];
#pragma unroll
        for (int j = 0; j < 8; j++) wv[j] = w0[(size_t)j * K + k];
#pragma unroll
        for (int i = 0; i < 4; i++)
#pragma unroll
            for (int j = 0; j < 8; j++) acc[i][j] = fmaf(xv[i], wv[j], acc[i][j]);
    }
#pragma unroll
    for (int o = 16; o; o >>= 1)
#pragma unroll
        for (int i = 0; i < 4; i++)
#pragma unroll
            for (int j = 0; j < 8; j++)
                acc[i][j] += __shfl_xor_sync(0xffffffffu, acc[i][j], o);
    int i = lane >> 3, j = lane & 7;
    float v = acc[i][j] + bias[ntile * 8 + j];
    if (doRelu) v = fmaxf(v, 0.f);
    Y[(size_t)(mtile * 4 + i) * N + ntile * 8 + j] = v;
}

// ---------------------------------------------------------------------------
// Attention + softmax -> fuse weights; final fuse.
// ---------------------------------------------------------------------------
__global__ void attn_kernel(const float* __restrict__ keys, const float* __restrict__ qq,
                            float* __restrict__ wf)
{
    int b = blockIdx.x;
    __shared__ float sA[5][5];
    int warp = threadIdx.x >> 5, lane = threadIdx.x & 31;
    for (int e = warp; e < 25; e += 8) {
        int i = e / 5, j = e - i * 5;
        const float4* kr = (const float4*)(keys + (size_t)(i * 32 + b) * 1024);
        const float4* qr = (const float4*)(qq + (size_t)(j * 32 + b) * 1024);
        float acc = 0.f;
        for (int k = lane; k < 256; k += 32) {
            float4 a = kr[k], c = qr[k];
            acc += a.x * c.x + a.y * c.y + a.z * c.z + a.w * c.w;
        }
#pragma unroll
        for (int o = 16; o; o >>= 1) acc += __shfl_xor_sync(0xffffffffu, acc, o);
        if (lane == 0) sA[i][j] = acc;
    }
    __syncthreads();
    if (threadIdx.x == 0) {
        float w[5] = {0.f, 0.f, 0.f, 0.f, 0.f};
        for (int j = 0; j < 5; j++) {
            float dd[4], mx = -1e30f;
            for (int r = 0; r < 4; r++) {
                dd[r] = (j > r) ? sA[r][j] : sA[r + 1][j];
                mx = fmaxf(mx, dd[r]);
            }
            float s = 0.f;
            for (int r = 0; r < 4; r++) { dd[r] = expf(dd[r] - mx); s += dd[r]; }
            float inv = 1.f / s;
            for (int r = 0; r < 4; r++) {
                int i = (j > r) ? r : r + 1;
                w[i] += dd[r] * inv;
            }
        }
        for (int i = 0; i < 5; i++) wf[b * 5 + i] = w[i] * 0.2f;
    }
}

__global__ void fuse_kernel(const float* __restrict__ bevs, const float* __restrict__ wf,
                            float* __restrict__ out)
{
    const int CHW = 256 * 16 * 16;
    int idx = blockIdx.x * blockDim.x + threadIdx.x;
    if (idx >= 32 * CHW) return;
    int b   = idx / CHW;
    int chw = idx - b * CHW;
    const float* base = bevs + ((size_t)b * 5) * CHW + chw;
    float acc = 0.f;
#pragma unroll
    for (int k = 0; k < 5; k++) acc += wf[b * 5 + k] * base[(size_t)k * CHW];
    out[idx] = acc;
}

// ---------------------------------------------------------------------------
extern "C" void kernel_launch(void* const* d_in, const int* in_sizes, int n_in,
                              void* d_out, int out_size)
{
    (void)in_sizes; (void)n_in; (void)out_size;
    const float* bevs = (const float*)d_in[0];
    const float *cw[5], *cs[5], *ct[5];
    for (int i = 0; i < 5; i++) {
        cw[i] = (const float*)d_in[1 + 3 * i];
        cs[i] = (const float*)d_in[2 + 3 * i];
        ct[i] = (const float*)d_in[3 + 3 * i];
    }
    const float* kw1 = (const float*)d_in[16]; const float* kb1 = (const float*)d_in[17];
    const float* kw2 = (const float*)d_in[18]; const float* kb2 = (const float*)d_in[19];
    const float* kw3 = (const float*)d_in[20]; const float* kb3 = (const float*)d_in[21];
    const float* qw1 = (const float*)d_in[22]; const float* qb1 = (const float*)d_in[23];
    const float* qw2 = (const float*)d_in[24]; const float* qb2 = (const float*)d_in[25];
    const float* qw3 = (const float*)d_in[26]; const float* qb3 = (const float*)d_in[27];
    const float* aw  = (const float*)d_in[28]; const float* ab  = (const float*)d_in[29];
    float* out = (float*)d_out;

    __half *a0h, *b1h, *b2h, *b3h, *b4h;
    cudaGetSymbolAddress((void**)&a0h, g_a0h);
    cudaGetSymbolAddress((void**)&b1h, g_b1h);
    cudaGetSymbolAddress((void**)&b2h, g_b2h);
    cudaGetSymbolAddress((void**)&b3h, g_b3h);
    cudaGetSymbolAddress((void**)&b4h, g_b4h);
    float *feat, *m1k, *m1q, *m2k, *m2q, *keys, *qrys, *qq, *wf;
    cudaGetSymbolAddress((void**)&feat, g_feat);
    cudaGetSymbolAddress((void**)&m1k, g_m1k);
    cudaGetSymbolAddress((void**)&m1q, g_m1q);
    cudaGetSymbolAddress((void**)&m2k, g_m2k);
    cudaGetSymbolAddress((void**)&m2q, g_m2q);
    cudaGetSymbolAddress((void**)&keys, g_keys);
    cudaGetSymbolAddress((void**)&qrys, g_qrys);
    cudaGetSymbolAddress((void**)&qq, g_qq);
    cudaGetSymbolAddress((void**)&wf, g_wf);
    __half *w1h, *w2h, *w3h, *w4h, *w5h;
    cudaGetSymbolAddress((void**)&w1h, g_w1h);
    cudaGetSymbolAddress((void**)&w2h, g_w2h);
    cudaGetSymbolAddress((void**)&w3h, g_w3h);
    cudaGetSymbolAddress((void**)&w4h, g_w4h);
    cudaGetSymbolAddress((void**)&w5h, g_w5h);

    // stage = (64+128)*144 = 27648B; 4 stages = 110592 -> 2 CTAs/SM
    constexpr int SMEM_S = 4 * 27648;

    cudaFuncSetAttribute(convMMA_kernel<256, 512, 16, 16, 1, 0, 64, 4, 2>,
                         cudaFuncAttributeMaxDynamicSharedMemorySize, SMEM_S);
    cudaFuncSetAttribute(convMMA_kernel<512, 256, 16, 16, 1, 0, 64, 4, 2>,
                         cudaFuncAttributeMaxDynamicSharedMemorySize, SMEM_S);
    cudaFuncSetAttribute(convMMA_kernel<256, 256, 16, 16, 2, 0, 64, 4, 2>,
                         cudaFuncAttributeMaxDynamicSharedMemorySize, SMEM_S);
    cudaFuncSetAttribute(convMMA_kernel<256, 256, 8, 8, 1, 0, 64, 4, 2>,
                         cudaFuncAttributeMaxDynamicSharedMemorySize, SMEM_S);
    cudaFuncSetAttribute(convMMA_kernel<256, 256, 8, 8, 2, 1, 64, 4, 2>,
                         cudaFuncAttributeMaxDynamicSharedMemorySize, SMEM_S);

    // ---- launch 0: all weight preps in one kernel ----
    {
        int t1 = 512 * 2304, t2 = 256 * 4608, t3 = 256 * 2304;
        WPrepDesc d0 = {cw[0], w1h, 256, t1, 0};
        WPrepDesc d1 = {cw[1], w2h, 512, t2, t1};
        WPrepDesc d2 = {cw[2], w3h, 256, t3, t1 + t2};
        WPrepDesc d3 = {cw[3], w4h, 256, t3, t1 + t2 + t3};
        WPrepDesc d4 = {cw[4], w5h, 256, t3, t1 + t2 + 2 * t3};
        int grand = t1 + t2 + 3 * t3;
        wprep_all_kernel<<<1184, 256>>>(d0, d1, d2, d3, d4, grand);
    }
    // ---- launch 1: bevs convert ----
    actsplit_kernel<<<dim3(160, 8), 256>>>(bevs, a0h);

    // ---- launches 2..6: conv stack ----
    convMMA_kernel<256, 512, 16, 16, 1, 0, 64, 4, 2><<<dim3(16, 160), 256, SMEM_S>>>(
        a0h, w1h, cs[0], ct[0], b1h, nullptr);
    convMMA_kernel<512, 256, 16, 16, 1, 0, 64, 4, 2><<<dim3(8, 160), 256, SMEM_S>>>(
        b1h, w2h, cs[1], ct[1], b2h, nullptr);
    convMMA_kernel<256, 256, 16, 16, 2, 0, 64, 4, 2><<<dim3(2, 160), 256, SMEM_S>>>(
        b2h, w3h, cs[2], ct[2], b3h, nullptr);
    convMMA_kernel<256, 256, 8, 8, 1, 0, 64, 4, 2><<<dim3(2, 160), 256, SMEM_S>>>(
        b3h, w4h, cs[3], ct[3], b4h, nullptr);
    convMMA_kernel<256, 256, 8, 8, 2, 1, 64, 4, 2><<<dim3(2, 40), 256, SMEM_S>>>(
        b4h, w5h, cs[4], ct[4], nullptr, feat);

    // ---- fused k/q tail ----
    auto wt2 = [&](const float* X1, const float* W1, const float* B1, float* Y1, int N1,
                   const float* X2, const float* W2, const float* B2, float* Y2, int N2,
                   int M, int K, int relu) {
        int warps = (M / 4) * ((N1 + N2) / 8);
        warptile2_kernel<<<(warps + 7) / 8, 256>>>(X1, W1, B1, Y1, N1,
                                                   X2, W2, B2, Y2, N2, M, K, relu);
    };
    wt2(feat, kw1, kb1, m1k, 256, feat, qw1, qb1, m1q, 256, 160, 4096, 1);
    wt2(m1k, kw2, kb2, m2k, 128, m1q, qw2, qb2, m2q, 128, 160, 256, 1);
    wt2(m2k, kw3, kb3, keys, 1024, m2q, qw3, qb3, qrys, 32, 160, 128, 0);
    {
        int warps = (160 / 4) * (1024 / 8);
        warptile_kernel<<<(warps + 7) / 8, 256>>>(qrys, aw, ab, qq, 160, 1024, 32, 0);
    }

    attn_kernel<<<32, 256>>>(keys, qq, wf);
    fuse_kernel<<<(32 * 256 * 16 * 16 + 255) / 256, 256>>>(bevs, wf, out);
}